// round 5
// baseline (speedup 1.0000x reference)
#include <cuda_runtime.h>

#define Bb 4
#define Cc 64
#define NN 4096    // 64*64 merged positions
#define HH 128
#define WW 128

// -------- scratch (static device globals; no allocations allowed) --------
__device__ float g_tn[Bb*NN*256];   // normalized merged features (B,N,256)
__device__ float g_c1[Bb*NN*Cc];    // (B,N,64)
__device__ float g_q [Bb*NN*Cc];
__device__ float g_k [Bb*NN*Cc];
__device__ float g_v [Bb*NN*Cc];
__device__ float g_q2[Bb*NN*Cc];
__device__ float g_k2[Bb*NN*Cc];
__device__ float g_o1[Bb*NN*Cc];    // attention-1 output (B,N,64)
__device__ float g_y [Bb*NN*Cc];    // pre-upsample output (B,N,64)
__device__ float g_s2[Bb*64*64];    // channel-attn raw scores
__device__ float g_M [Bb*64*64];    // w1_right @ softmax(scores)

// =====================================================================
// K1a: patch-merge (space-to-depth 2x2) + LayerNorm over 256 channels
// grid: (half=2, hh=64, b=4), block 256
// =====================================================================
__global__ void k_merge_ln(const float* __restrict__ x,
                           const float* __restrict__ gamma,
                           const float* __restrict__ beta) {
    __shared__ float ts[256][33];
    __shared__ float s_mu[32], s_rs[32];
    int b    = blockIdx.z;
    int hh   = blockIdx.y;
    int half = blockIdx.x;
    int tid  = threadIdx.x;

    // load 256 channels x 32 positions (ww = half*32 + p)
    for (int e = tid; e < 256 * 32; e += 256) {
        int c = e >> 5;
        int p = e & 31;
        int ww = half * 32 + p;
        int qd = c >> 6, ch = c & 63;
        int dr = qd & 1, dc = (qd >> 1) & 1;   // order: x0(0,0) x1(1,0) x2(0,1) x3(1,1)
        ts[c][p] = x[(((b * 64 + ch) * 128) + 2 * hh + dr) * 128 + 2 * ww + dc];
    }
    __syncthreads();

    int w = tid >> 5, lane = tid & 31;
    for (int p = w * 4; p < w * 4 + 4; p++) {
        float s = 0.f, ss = 0.f;
        for (int c = lane; c < 256; c += 32) {
            float v = ts[c][p];
            s += v; ss += v * v;
        }
        #pragma unroll
        for (int off = 16; off; off >>= 1) {
            s  += __shfl_xor_sync(0xffffffffu, s,  off);
            ss += __shfl_xor_sync(0xffffffffu, ss, off);
        }
        float mu  = s * (1.f / 256.f);
        float var = ss * (1.f / 256.f) - mu * mu;
        if (lane == 0) { s_mu[p] = mu; s_rs[p] = rsqrtf(var + 1e-5f); }
    }
    __syncthreads();

    int n0 = hh * 64 + half * 32;
    for (int e = tid; e < 32 * 256; e += 256) {
        int p = e >> 8;
        int c = e & 255;
        float v = (ts[c][p] - s_mu[p]) * s_rs[p] * gamma[c] + beta[c];
        g_tn[(size_t)(b * NN + n0 + p) * 256 + c] = v;
    }
}

// =====================================================================
// K1b: c1 = tn @ pm_w^T + pm_b   (N x 256) x (256 -> 64)
// grid: (ptile=64, b=4), block 256
// =====================================================================
__global__ void k_pmlinear(const float* __restrict__ pm_w,
                           const float* __restrict__ pm_b) {
    __shared__ float As[64][68];
    __shared__ float Ws[64][65];
    int b  = blockIdx.y;
    int p0 = blockIdx.x * 64;
    int tid = threadIdx.x;
    int tx = tid & 15, ty = tid >> 4;
    float acc[4][4] = {};

    for (int kc = 0; kc < 4; kc++) {
        __syncthreads();
        int cg = tid & 15, r0 = tid >> 4;
        for (int rr = r0; rr < 64; rr += 16) {
            float4 av = *(const float4*)&g_tn[(size_t)(b * NN + p0 + rr) * 256 + kc * 64 + cg * 4];
            *(float4*)&As[rr][cg * 4] = av;
            float4 wv = *(const float4*)&pm_w[rr * 256 + kc * 64 + cg * 4];
            Ws[rr][cg * 4 + 0] = wv.x; Ws[rr][cg * 4 + 1] = wv.y;
            Ws[rr][cg * 4 + 2] = wv.z; Ws[rr][cg * 4 + 3] = wv.w;
        }
        __syncthreads();
        #pragma unroll 8
        for (int c = 0; c < 64; c++) {
            float a[4], wv[4];
            #pragma unroll
            for (int i = 0; i < 4; i++) a[i]  = As[ty * 4 + i][c];
            #pragma unroll
            for (int j = 0; j < 4; j++) wv[j] = Ws[tx * 4 + j][c];
            #pragma unroll
            for (int i = 0; i < 4; i++)
                #pragma unroll
                for (int j = 0; j < 4; j++)
                    acc[i][j] += a[i] * wv[j];
        }
    }
    #pragma unroll
    for (int i = 0; i < 4; i++) {
        float4 o;
        o.x = acc[i][0] + pm_b[tx * 4 + 0];
        o.y = acc[i][1] + pm_b[tx * 4 + 1];
        o.z = acc[i][2] + pm_b[tx * 4 + 2];
        o.w = acc[i][3] + pm_b[tx * 4 + 3];
        *(float4*)&g_c1[(size_t)(b * NN + p0 + ty * 4 + i) * 64 + tx * 4] = o;
    }
}

// =====================================================================
// K2: 5 projections q,k,v,q2,k2 = c1 @ wX^T + bX
// grid: (ptile=64, b=4, wi=5), block 256
// =====================================================================
__global__ void k_qkv(const float* w2, const float* b2,
                      const float* w3, const float* b3,
                      const float* w4, const float* b4,
                      const float* w5, const float* b5,
                      const float* w6, const float* b6) {
    __shared__ float As[64][68];
    __shared__ float Ws[64][65];
    int b  = blockIdx.y;
    int p0 = blockIdx.x * 64;
    int wi = blockIdx.z;
    const float* wp; const float* bp; float* outp;
    switch (wi) {
        case 0: wp = w2; bp = b2; outp = g_q;  break;
        case 1: wp = w3; bp = b3; outp = g_k;  break;
        case 2: wp = w4; bp = b4; outp = g_v;  break;
        case 3: wp = w5; bp = b5; outp = g_q2; break;
        default: wp = w6; bp = b6; outp = g_k2; break;
    }
    int tid = threadIdx.x;
    int tx = tid & 15, ty = tid >> 4;
    int cg = tid & 15, r0 = tid >> 4;
    for (int rr = r0; rr < 64; rr += 16) {
        float4 av = *(const float4*)&g_c1[(size_t)(b * NN + p0 + rr) * 64 + cg * 4];
        *(float4*)&As[rr][cg * 4] = av;
        float4 wv = *(const float4*)&wp[rr * 64 + cg * 4];
        Ws[rr][cg * 4 + 0] = wv.x; Ws[rr][cg * 4 + 1] = wv.y;
        Ws[rr][cg * 4 + 2] = wv.z; Ws[rr][cg * 4 + 3] = wv.w;
    }
    __syncthreads();
    float acc[4][4] = {};
    #pragma unroll 8
    for (int c = 0; c < 64; c++) {
        float a[4], wv[4];
        #pragma unroll
        for (int i = 0; i < 4; i++) a[i]  = As[ty * 4 + i][c];
        #pragma unroll
        for (int j = 0; j < 4; j++) wv[j] = Ws[tx * 4 + j][c];
        #pragma unroll
        for (int i = 0; i < 4; i++)
            #pragma unroll
            for (int j = 0; j < 4; j++)
                acc[i][j] += a[i] * wv[j];
    }
    #pragma unroll
    for (int i = 0; i < 4; i++) {
        float4 o;
        o.x = acc[i][0] + bp[tx * 4 + 0];
        o.y = acc[i][1] + bp[tx * 4 + 1];
        o.z = acc[i][2] + bp[tx * 4 + 2];
        o.w = acc[i][3] + bp[tx * 4 + 3];
        *(float4*)&outp[(size_t)(b * NN + p0 + ty * 4 + i) * 64 + tx * 4] = o;
    }
}

// =====================================================================
// K3: flash attention 1 (fp32). BM=128, BN=64, d=64, 256 threads,
// 8x4 microtile (ty->8 rows, tx->4 cols / 4 channels).
// grid: (N/128=32, b=4), dynamic smem 104448 B
// =====================================================================
extern __shared__ float smem3[];
__global__ void __launch_bounds__(256, 1) k_attn1() {
    float* Qs  = smem3;                  // [128][68]
    float* Kst = Qs  + 128 * 68;         // [c][n]  64*68
    float* Vs  = Kst + 64 * 68;          // [n][c]  64*68
    float* Ps  = Vs  + 64 * 68;          // [128][68]

    int b   = blockIdx.y;
    int m0  = blockIdx.x * 128;
    int tid = threadIdx.x;
    int tx  = tid & 15, ty = tid >> 4;

    const float* Qg = g_q + (size_t)(b * NN + m0) * 64;
    const float* Kg = g_k + (size_t)b * NN * 64;
    const float* Vg = g_v + (size_t)b * NN * 64;

    {   // load Q tile
        int cg = tid & 15, r0 = tid >> 4;
        for (int r = r0; r < 128; r += 16)
            *(float4*)&Qs[r * 68 + cg * 4] = *(const float4*)&Qg[r * 64 + cg * 4];
    }

    float O[8][4] = {};
    float mrow[8], lrow[8];
    #pragma unroll
    for (int r = 0; r < 8; r++) { mrow[r] = -3.0e38f; lrow[r] = 0.f; }

    for (int n0 = 0; n0 < NN; n0 += 64) {
        __syncthreads();   // previous PV done; safe to overwrite K/V/P
        {
            int cg = tid & 15, r0 = tid >> 4;
            for (int r = r0; r < 64; r += 16) {
                float4 kv = *(const float4*)&Kg[(size_t)(n0 + r) * 64 + cg * 4];
                Kst[(cg * 4 + 0) * 68 + r] = kv.x;
                Kst[(cg * 4 + 1) * 68 + r] = kv.y;
                Kst[(cg * 4 + 2) * 68 + r] = kv.z;
                Kst[(cg * 4 + 3) * 68 + r] = kv.w;
                *(float4*)&Vs[r * 68 + cg * 4] =
                    *(const float4*)&Vg[(size_t)(n0 + r) * 64 + cg * 4];
            }
        }
        __syncthreads();

        // ---- S = Q K^T (8x4 per thread) ----
        float S[8][4] = {};
        #pragma unroll 4
        for (int c = 0; c < 64; c += 4) {
            float4 kf0 = *(float4*)&Kst[(c + 0) * 68 + tx * 4];
            float4 kf1 = *(float4*)&Kst[(c + 1) * 68 + tx * 4];
            float4 kf2 = *(float4*)&Kst[(c + 2) * 68 + tx * 4];
            float4 kf3 = *(float4*)&Kst[(c + 3) * 68 + tx * 4];
            #pragma unroll
            for (int r = 0; r < 8; r++) {
                float4 qf = *(float4*)&Qs[(ty * 8 + r) * 68 + c];
                S[r][0] += qf.x * kf0.x + qf.y * kf1.x + qf.z * kf2.x + qf.w * kf3.x;
                S[r][1] += qf.x * kf0.y + qf.y * kf1.y + qf.z * kf2.y + qf.w * kf3.y;
                S[r][2] += qf.x * kf0.z + qf.y * kf1.z + qf.z * kf2.z + qf.w * kf3.z;
                S[r][3] += qf.x * kf0.w + qf.y * kf1.w + qf.z * kf2.w + qf.w * kf3.w;
            }
        }

        // ---- online softmax (rows span the 16 tx lanes) ----
        #pragma unroll
        for (int r = 0; r < 8; r++) {
            float tm = fmaxf(fmaxf(S[r][0], S[r][1]), fmaxf(S[r][2], S[r][3]));
            #pragma unroll
            for (int off = 8; off; off >>= 1)
                tm = fmaxf(tm, __shfl_xor_sync(0xffffffffu, tm, off));
            float mn = fmaxf(mrow[r], tm);
            float alpha = __expf(mrow[r] - mn);
            mrow[r] = mn;
            float rs = 0.f;
            #pragma unroll
            for (int j = 0; j < 4; j++) { S[r][j] = __expf(S[r][j] - mn); rs += S[r][j]; }
            #pragma unroll
            for (int off = 8; off; off >>= 1)
                rs += __shfl_xor_sync(0xffffffffu, rs, off);
            lrow[r] = lrow[r] * alpha + rs;
            #pragma unroll
            for (int j = 0; j < 4; j++) O[r][j] *= alpha;
            *(float4*)&Ps[(ty * 8 + r) * 68 + tx * 4] =
                make_float4(S[r][0], S[r][1], S[r][2], S[r][3]);
        }
        __syncthreads();

        // ---- O += P V  (channels ch = tx*4 + j) ----
        #pragma unroll 2
        for (int n = 0; n < 64; n += 4) {
            float4 vf0 = *(float4*)&Vs[(n + 0) * 68 + tx * 4];
            float4 vf1 = *(float4*)&Vs[(n + 1) * 68 + tx * 4];
            float4 vf2 = *(float4*)&Vs[(n + 2) * 68 + tx * 4];
            float4 vf3 = *(float4*)&Vs[(n + 3) * 68 + tx * 4];
            #pragma unroll
            for (int r = 0; r < 8; r++) {
                float4 pf = *(float4*)&Ps[(ty * 8 + r) * 68 + n];
                O[r][0] += pf.x * vf0.x + pf.y * vf1.x + pf.z * vf2.x + pf.w * vf3.x;
                O[r][1] += pf.x * vf0.y + pf.y * vf1.y + pf.z * vf2.y + pf.w * vf3.y;
                O[r][2] += pf.x * vf0.z + pf.y * vf1.z + pf.z * vf2.z + pf.w * vf3.z;
                O[r][3] += pf.x * vf0.w + pf.y * vf1.w + pf.z * vf2.w + pf.w * vf3.w;
            }
        }
    }

    #pragma unroll
    for (int r = 0; r < 8; r++) {
        float inv = 1.f / lrow[r];
        *(float4*)&g_o1[(size_t)(b * NN + m0 + ty * 8 + r) * 64 + tx * 4] =
            make_float4(O[r][0] * inv, O[r][1] * inv, O[r][2] * inv, O[r][3] * inv);
    }
}

// =====================================================================
// K4: channel attention scores s2[c][d] = sum_n q2[n,c]*k2[n,d]
// =====================================================================
__global__ void k_zero() {
    int i = blockIdx.x * 256 + threadIdx.x;
    if (i < Bb * 4096) g_s2[i] = 0.f;
}

__global__ void k_chscore() {
    __shared__ float Qs[64][68];
    __shared__ float Ks[64][68];
    int b  = blockIdx.y;
    int n0 = blockIdx.x * 64;
    int tid = threadIdx.x;
    int cg = tid & 15, r0 = tid >> 4;
    for (int rr = r0; rr < 64; rr += 16) {
        *(float4*)&Qs[rr][cg * 4] =
            *(const float4*)&g_q2[(size_t)(b * NN + n0 + rr) * 64 + cg * 4];
        *(float4*)&Ks[rr][cg * 4] =
            *(const float4*)&g_k2[(size_t)(b * NN + n0 + rr) * 64 + cg * 4];
    }
    __syncthreads();
    int tx = tid & 15, ty = tid >> 4;   // ty -> c group, tx -> d group
    float acc[4][4] = {};
    #pragma unroll 4
    for (int n = 0; n < 64; n++) {
        float4 qf = *(float4*)&Qs[n][ty * 4];
        float4 kf = *(float4*)&Ks[n][tx * 4];
        float qa[4] = {qf.x, qf.y, qf.z, qf.w};
        float ka[4] = {kf.x, kf.y, kf.z, kf.w};
        #pragma unroll
        for (int i = 0; i < 4; i++)
            #pragma unroll
            for (int j = 0; j < 4; j++)
                acc[i][j] += qa[i] * ka[j];
    }
    #pragma unroll
    for (int i = 0; i < 4; i++)
        #pragma unroll
        for (int j = 0; j < 4; j++)
            atomicAdd(&g_s2[b * 4096 + (ty * 4 + i) * 64 + tx * 4 + j], acc[i][j]);
}

// softmax over d + M = w1_right @ softmax.  grid: b=4, block 256
__global__ void k_chsoftmax_M(const float* __restrict__ w1) {
    __shared__ float qn[64][65];
    int b = blockIdx.x;
    int tid = threadIdx.x;
    int w = tid >> 5, lane = tid & 31;
    for (int r = w; r < 64; r += 8) {
        float v0 = g_s2[b * 4096 + r * 64 + lane];
        float v1 = g_s2[b * 4096 + r * 64 + 32 + lane];
        float m = fmaxf(v0, v1);
        #pragma unroll
        for (int off = 16; off; off >>= 1)
            m = fmaxf(m, __shfl_xor_sync(0xffffffffu, m, off));
        float e0 = __expf(v0 - m), e1 = __expf(v1 - m);
        float s = e0 + e1;
        #pragma unroll
        for (int off = 16; off; off >>= 1)
            s += __shfl_xor_sync(0xffffffffu, s, off);
        float inv = 1.f / s;
        qn[r][lane] = e0 * inv;
        qn[r][lane + 32] = e1 * inv;
    }
    __syncthreads();
    int tx = tid & 15, ty = tid >> 4;   // ty -> o group, tx -> d group
    float acc[4][4] = {};
    #pragma unroll 4
    for (int c = 0; c < 64; c++) {
        float wv[4], qv[4];
        #pragma unroll
        for (int i = 0; i < 4; i++) wv[i] = w1[(ty * 4 + i) * 128 + 64 + c];
        #pragma unroll
        for (int j = 0; j < 4; j++) qv[j] = qn[c][tx * 4 + j];
        #pragma unroll
        for (int i = 0; i < 4; i++)
            #pragma unroll
            for (int j = 0; j < 4; j++)
                acc[i][j] += wv[i] * qv[j];
    }
    #pragma unroll
    for (int i = 0; i < 4; i++)
        #pragma unroll
        for (int j = 0; j < 4; j++)
            g_M[b * 4096 + (ty * 4 + i) * 64 + tx * 4 + j] = acc[i][j];
}

// =====================================================================
// K5: y = w1_left @ out1 + M @ v + b1.  grid (ptile=64, b=4)
// =====================================================================
__global__ void k_proj(const float* __restrict__ w1, const float* __restrict__ b1) {
    __shared__ float As[64][68];
    __shared__ float Ws[64][65];
    int b  = blockIdx.y;
    int p0 = blockIdx.x * 64;
    int tid = threadIdx.x;
    int tx = tid & 15, ty = tid >> 4;
    float acc[4][4] = {};

    for (int ph = 0; ph < 2; ph++) {
        __syncthreads();
        int cg = tid & 15, r0 = tid >> 4;
        for (int rr = r0; rr < 64; rr += 16) {
            float4 av, wv;
            if (ph == 0) {
                av = *(const float4*)&g_o1[(size_t)(b * NN + p0 + rr) * 64 + cg * 4];
                wv = *(const float4*)&w1[rr * 128 + cg * 4];
            } else {
                av = *(const float4*)&g_v[(size_t)(b * NN + p0 + rr) * 64 + cg * 4];
                wv = *(const float4*)&g_M[b * 4096 + rr * 64 + cg * 4];
            }
            *(float4*)&As[rr][cg * 4] = av;
            Ws[rr][cg * 4 + 0] = wv.x; Ws[rr][cg * 4 + 1] = wv.y;
            Ws[rr][cg * 4 + 2] = wv.z; Ws[rr][cg * 4 + 3] = wv.w;
        }
        __syncthreads();
        #pragma unroll 8
        for (int c = 0; c < 64; c++) {
            float a[4], wv[4];
            #pragma unroll
            for (int i = 0; i < 4; i++) a[i]  = As[ty * 4 + i][c];
            #pragma unroll
            for (int j = 0; j < 4; j++) wv[j] = Ws[tx * 4 + j][c];
            #pragma unroll
            for (int i = 0; i < 4; i++)
                #pragma unroll
                for (int j = 0; j < 4; j++)
                    acc[i][j] += a[i] * wv[j];
        }
    }
    #pragma unroll
    for (int i = 0; i < 4; i++) {
        float4 o;
        o.x = acc[i][0] + b1[tx * 4 + 0];
        o.y = acc[i][1] + b1[tx * 4 + 1];
        o.z = acc[i][2] + b1[tx * 4 + 2];
        o.w = acc[i][3] + b1[tx * 4 + 3];
        *(float4*)&g_y[(size_t)(b * NN + p0 + ty * 4 + i) * 64 + tx * 4] = o;
    }
}

// =====================================================================
// K6: bilinear 2x upsample (half-pixel centers, edge clamp) + residual
// =====================================================================
__global__ void k_upsample(const float* __restrict__ x, float* __restrict__ out) {
    int idx = blockIdx.x * 256 + threadIdx.x;
    if (idx >= Bb * Cc * HH * WW) return;
    int j = idx & 127;
    int i = (idx >> 7) & 127;
    int c = (idx >> 14) & 63;
    int b = idx >> 20;
    int p = i >> 1, q = j >> 1;
    int r0, r1; float wy0, wy1;
    if (i & 1) { r0 = p; r1 = (p + 1 < 64) ? p + 1 : 63; wy0 = 0.75f; wy1 = 0.25f; }
    else       { r0 = (p > 0) ? p - 1 : 0; r1 = p;       wy0 = 0.25f; wy1 = 0.75f; }
    int s0, s1; float wx0, wx1;
    if (j & 1) { s0 = q; s1 = (q + 1 < 64) ? q + 1 : 63; wx0 = 0.75f; wx1 = 0.25f; }
    else       { s0 = (q > 0) ? q - 1 : 0; s1 = q;       wx0 = 0.25f; wx1 = 0.75f; }
    const float* yb = g_y + (size_t)b * NN * 64;
    float v = wy0 * (wx0 * yb[(r0 * 64 + s0) * 64 + c] + wx1 * yb[(r0 * 64 + s1) * 64 + c])
            + wy1 * (wx0 * yb[(r1 * 64 + s0) * 64 + c] + wx1 * yb[(r1 * 64 + s1) * 64 + c]);
    out[idx] = v + x[idx];
}

// =====================================================================
extern "C" void kernel_launch(void* const* d_in, const int* in_sizes, int n_in,
                              void* d_out, int out_size) {
    const float* x        = (const float*)d_in[0];
    const float* pm_gamma = (const float*)d_in[1];
    const float* pm_beta  = (const float*)d_in[2];
    const float* pm_w     = (const float*)d_in[3];
    const float* pm_b     = (const float*)d_in[4];
    const float* w2 = (const float*)d_in[5];
    const float* b2 = (const float*)d_in[6];
    const float* w3 = (const float*)d_in[7];
    const float* b3 = (const float*)d_in[8];
    const float* w4 = (const float*)d_in[9];
    const float* b4 = (const float*)d_in[10];
    const float* w5 = (const float*)d_in[11];
    const float* b5 = (const float*)d_in[12];
    const float* w6 = (const float*)d_in[13];
    const float* b6 = (const float*)d_in[14];
    const float* w1 = (const float*)d_in[15];
    const float* b1 = (const float*)d_in[16];
    float* out = (float*)d_out;

    const int attn_smem = (128 * 68 + 64 * 68 + 64 * 68 + 128 * 68) * 4;  // 104448 B
    cudaFuncSetAttribute(k_attn1, cudaFuncAttributeMaxDynamicSharedMemorySize, attn_smem);

    k_merge_ln   <<<dim3(2, 64, Bb), 256>>>(x, pm_gamma, pm_beta);
    k_pmlinear   <<<dim3(64, Bb),    256>>>(pm_w, pm_b);
    k_qkv        <<<dim3(64, Bb, 5), 256>>>(w2, b2, w3, b3, w4, b4, w5, b5, w6, b6);
    k_zero       <<<64, 256>>>();
    k_attn1      <<<dim3(32, Bb), 256, attn_smem>>>();
    k_chscore    <<<dim3(64, Bb), 256>>>();
    k_chsoftmax_M<<<Bb, 256>>>(w1);
    k_proj       <<<dim3(64, Bb), 256>>>(w1, b1);
    k_upsample   <<<(Bb * Cc * HH * WW) / 256, 256>>>(x, out);
}

// round 6
// speedup vs baseline: 1.0035x; 1.0035x over previous
#include <cuda_runtime.h>

#define Bb 4
#define Cc 64
#define NN 4096    // 64*64 merged positions
#define HH 128
#define WW 128

// -------- scratch (static device globals; no allocations allowed) --------
__device__ float g_tn[Bb*NN*256];   // normalized merged features (B,N,256)
__device__ float g_c1[Bb*NN*Cc];    // (B,N,64)
__device__ float g_q [Bb*NN*Cc];
__device__ float g_k [Bb*NN*Cc];
__device__ float g_v [Bb*NN*Cc];
__device__ float g_q2[Bb*NN*Cc];
__device__ float g_k2[Bb*NN*Cc];
__device__ float g_o1[Bb*NN*Cc];    // attention-1 output (B,N,64)
__device__ float g_y [Bb*NN*Cc];    // pre-upsample output (B,N,64)
__device__ float g_s2[Bb*64*64];    // channel-attn raw scores
__device__ float g_M [Bb*64*64];    // w1_right @ softmax(scores)

// =====================================================================
// K1a: patch-merge (space-to-depth 2x2) + LayerNorm over 256 channels
// grid: (half=2, hh=64, b=4), block 256
// =====================================================================
__global__ void k_merge_ln(const float* __restrict__ x,
                           const float* __restrict__ gamma,
                           const float* __restrict__ beta) {
    __shared__ float ts[256][33];
    __shared__ float s_mu[32], s_rs[32];
    int b    = blockIdx.z;
    int hh   = blockIdx.y;
    int half = blockIdx.x;
    int tid  = threadIdx.x;

    // load 256 channels x 32 positions (ww = half*32 + p)
    for (int e = tid; e < 256 * 32; e += 256) {
        int c = e >> 5;
        int p = e & 31;
        int ww = half * 32 + p;
        int qd = c >> 6, ch = c & 63;
        int dr = qd & 1, dc = (qd >> 1) & 1;   // order: x0(0,0) x1(1,0) x2(0,1) x3(1,1)
        ts[c][p] = x[(((b * 64 + ch) * 128) + 2 * hh + dr) * 128 + 2 * ww + dc];
    }
    __syncthreads();

    int w = tid >> 5, lane = tid & 31;
    for (int p = w * 4; p < w * 4 + 4; p++) {
        float s = 0.f, ss = 0.f;
        for (int c = lane; c < 256; c += 32) {
            float v = ts[c][p];
            s += v; ss += v * v;
        }
        #pragma unroll
        for (int off = 16; off; off >>= 1) {
            s  += __shfl_xor_sync(0xffffffffu, s,  off);
            ss += __shfl_xor_sync(0xffffffffu, ss, off);
        }
        float mu  = s * (1.f / 256.f);
        float var = ss * (1.f / 256.f) - mu * mu;
        if (lane == 0) { s_mu[p] = mu; s_rs[p] = rsqrtf(var + 1e-5f); }
    }
    __syncthreads();

    int n0 = hh * 64 + half * 32;
    for (int e = tid; e < 32 * 256; e += 256) {
        int p = e >> 8;
        int c = e & 255;
        float v = (ts[c][p] - s_mu[p]) * s_rs[p] * gamma[c] + beta[c];
        g_tn[(size_t)(b * NN + n0 + p) * 256 + c] = v;
    }
}

// =====================================================================
// K1b: c1 = tn @ pm_w^T + pm_b   (N x 256) x (256 -> 64)
// grid: (ptile=64, b=4), block 256
// =====================================================================
__global__ void k_pmlinear(const float* __restrict__ pm_w,
                           const float* __restrict__ pm_b) {
    __shared__ float As[64][68];
    __shared__ float Ws[64][65];
    int b  = blockIdx.y;
    int p0 = blockIdx.x * 64;
    int tid = threadIdx.x;
    int tx = tid & 15, ty = tid >> 4;
    float acc[4][4] = {};

    for (int kc = 0; kc < 4; kc++) {
        __syncthreads();
        int cg = tid & 15, r0 = tid >> 4;
        for (int rr = r0; rr < 64; rr += 16) {
            float4 av = *(const float4*)&g_tn[(size_t)(b * NN + p0 + rr) * 256 + kc * 64 + cg * 4];
            *(float4*)&As[rr][cg * 4] = av;
            float4 wv = *(const float4*)&pm_w[rr * 256 + kc * 64 + cg * 4];
            Ws[rr][cg * 4 + 0] = wv.x; Ws[rr][cg * 4 + 1] = wv.y;
            Ws[rr][cg * 4 + 2] = wv.z; Ws[rr][cg * 4 + 3] = wv.w;
        }
        __syncthreads();
        #pragma unroll 8
        for (int c = 0; c < 64; c++) {
            float a[4], wv[4];
            #pragma unroll
            for (int i = 0; i < 4; i++) a[i]  = As[ty * 4 + i][c];
            #pragma unroll
            for (int j = 0; j < 4; j++) wv[j] = Ws[tx * 4 + j][c];
            #pragma unroll
            for (int i = 0; i < 4; i++)
                #pragma unroll
                for (int j = 0; j < 4; j++)
                    acc[i][j] += a[i] * wv[j];
        }
    }
    #pragma unroll
    for (int i = 0; i < 4; i++) {
        float4 o;
        o.x = acc[i][0] + pm_b[tx * 4 + 0];
        o.y = acc[i][1] + pm_b[tx * 4 + 1];
        o.z = acc[i][2] + pm_b[tx * 4 + 2];
        o.w = acc[i][3] + pm_b[tx * 4 + 3];
        *(float4*)&g_c1[(size_t)(b * NN + p0 + ty * 4 + i) * 64 + tx * 4] = o;
    }
}

// =====================================================================
// K2: 5 projections q,k,v,q2,k2 = c1 @ wX^T + bX
// grid: (ptile=64, b=4, wi=5), block 256
// =====================================================================
__global__ void k_qkv(const float* w2, const float* b2,
                      const float* w3, const float* b3,
                      const float* w4, const float* b4,
                      const float* w5, const float* b5,
                      const float* w6, const float* b6) {
    __shared__ float As[64][68];
    __shared__ float Ws[64][65];
    int b  = blockIdx.y;
    int p0 = blockIdx.x * 64;
    int wi = blockIdx.z;
    const float* wp; const float* bp; float* outp;
    switch (wi) {
        case 0: wp = w2; bp = b2; outp = g_q;  break;
        case 1: wp = w3; bp = b3; outp = g_k;  break;
        case 2: wp = w4; bp = b4; outp = g_v;  break;
        case 3: wp = w5; bp = b5; outp = g_q2; break;
        default: wp = w6; bp = b6; outp = g_k2; break;
    }
    int tid = threadIdx.x;
    int tx = tid & 15, ty = tid >> 4;
    int cg = tid & 15, r0 = tid >> 4;
    for (int rr = r0; rr < 64; rr += 16) {
        float4 av = *(const float4*)&g_c1[(size_t)(b * NN + p0 + rr) * 64 + cg * 4];
        *(float4*)&As[rr][cg * 4] = av;
        float4 wv = *(const float4*)&wp[rr * 64 + cg * 4];
        Ws[rr][cg * 4 + 0] = wv.x; Ws[rr][cg * 4 + 1] = wv.y;
        Ws[rr][cg * 4 + 2] = wv.z; Ws[rr][cg * 4 + 3] = wv.w;
    }
    __syncthreads();
    float acc[4][4] = {};
    #pragma unroll 8
    for (int c = 0; c < 64; c++) {
        float a[4], wv[4];
        #pragma unroll
        for (int i = 0; i < 4; i++) a[i]  = As[ty * 4 + i][c];
        #pragma unroll
        for (int j = 0; j < 4; j++) wv[j] = Ws[tx * 4 + j][c];
        #pragma unroll
        for (int i = 0; i < 4; i++)
            #pragma unroll
            for (int j = 0; j < 4; j++)
                acc[i][j] += a[i] * wv[j];
    }
    #pragma unroll
    for (int i = 0; i < 4; i++) {
        float4 o;
        o.x = acc[i][0] + bp[tx * 4 + 0];
        o.y = acc[i][1] + bp[tx * 4 + 1];
        o.z = acc[i][2] + bp[tx * 4 + 2];
        o.w = acc[i][3] + bp[tx * 4 + 3];
        *(float4*)&outp[(size_t)(b * NN + p0 + ty * 4 + i) * 64 + tx * 4] = o;
    }
}

// =====================================================================
// K3: flash attention 1 (fp32). BM=128, BN=64, d=64, 256 threads,
// 8x4 microtile (ty->8 rows, tx->4 cols / 4 channels).
// grid: (N/128=32, b=4), dynamic smem 104448 B
// =====================================================================
extern __shared__ float smem3[];
__global__ void __launch_bounds__(256, 1) k_attn1() {
    float* Qs  = smem3;                  // [128][68]
    float* Kst = Qs  + 128 * 68;         // [c][n]  64*68
    float* Vs  = Kst + 64 * 68;          // [n][c]  64*68
    float* Ps  = Vs  + 64 * 68;          // [128][68]

    int b   = blockIdx.y;
    int m0  = blockIdx.x * 128;
    int tid = threadIdx.x;
    int tx  = tid & 15, ty = tid >> 4;

    const float* Qg = g_q + (size_t)(b * NN + m0) * 64;
    const float* Kg = g_k + (size_t)b * NN * 64;
    const float* Vg = g_v + (size_t)b * NN * 64;

    {   // load Q tile
        int cg = tid & 15, r0 = tid >> 4;
        for (int r = r0; r < 128; r += 16)
            *(float4*)&Qs[r * 68 + cg * 4] = *(const float4*)&Qg[r * 64 + cg * 4];
    }

    float O[8][4] = {};
    float mrow[8], lrow[8];
    #pragma unroll
    for (int r = 0; r < 8; r++) { mrow[r] = -3.0e38f; lrow[r] = 0.f; }

    for (int n0 = 0; n0 < NN; n0 += 64) {
        __syncthreads();   // previous PV done; safe to overwrite K/V/P
        {
            int cg = tid & 15, r0 = tid >> 4;
            for (int r = r0; r < 64; r += 16) {
                float4 kv = *(const float4*)&Kg[(size_t)(n0 + r) * 64 + cg * 4];
                Kst[(cg * 4 + 0) * 68 + r] = kv.x;
                Kst[(cg * 4 + 1) * 68 + r] = kv.y;
                Kst[(cg * 4 + 2) * 68 + r] = kv.z;
                Kst[(cg * 4 + 3) * 68 + r] = kv.w;
                *(float4*)&Vs[r * 68 + cg * 4] =
                    *(const float4*)&Vg[(size_t)(n0 + r) * 64 + cg * 4];
            }
        }
        __syncthreads();

        // ---- S = Q K^T (8x4 per thread) ----
        float S[8][4] = {};
        #pragma unroll 4
        for (int c = 0; c < 64; c += 4) {
            float4 kf0 = *(float4*)&Kst[(c + 0) * 68 + tx * 4];
            float4 kf1 = *(float4*)&Kst[(c + 1) * 68 + tx * 4];
            float4 kf2 = *(float4*)&Kst[(c + 2) * 68 + tx * 4];
            float4 kf3 = *(float4*)&Kst[(c + 3) * 68 + tx * 4];
            #pragma unroll
            for (int r = 0; r < 8; r++) {
                float4 qf = *(float4*)&Qs[(ty * 8 + r) * 68 + c];
                S[r][0] += qf.x * kf0.x + qf.y * kf1.x + qf.z * kf2.x + qf.w * kf3.x;
                S[r][1] += qf.x * kf0.y + qf.y * kf1.y + qf.z * kf2.y + qf.w * kf3.y;
                S[r][2] += qf.x * kf0.z + qf.y * kf1.z + qf.z * kf2.z + qf.w * kf3.z;
                S[r][3] += qf.x * kf0.w + qf.y * kf1.w + qf.z * kf2.w + qf.w * kf3.w;
            }
        }

        // ---- online softmax (rows span the 16 tx lanes) ----
        #pragma unroll
        for (int r = 0; r < 8; r++) {
            float tm = fmaxf(fmaxf(S[r][0], S[r][1]), fmaxf(S[r][2], S[r][3]));
            #pragma unroll
            for (int off = 8; off; off >>= 1)
                tm = fmaxf(tm, __shfl_xor_sync(0xffffffffu, tm, off));
            float mn = fmaxf(mrow[r], tm);
            float alpha = __expf(mrow[r] - mn);
            mrow[r] = mn;
            float rs = 0.f;
            #pragma unroll
            for (int j = 0; j < 4; j++) { S[r][j] = __expf(S[r][j] - mn); rs += S[r][j]; }
            #pragma unroll
            for (int off = 8; off; off >>= 1)
                rs += __shfl_xor_sync(0xffffffffu, rs, off);
            lrow[r] = lrow[r] * alpha + rs;
            #pragma unroll
            for (int j = 0; j < 4; j++) O[r][j] *= alpha;
            *(float4*)&Ps[(ty * 8 + r) * 68 + tx * 4] =
                make_float4(S[r][0], S[r][1], S[r][2], S[r][3]);
        }
        __syncthreads();

        // ---- O += P V  (channels ch = tx*4 + j) ----
        #pragma unroll 2
        for (int n = 0; n < 64; n += 4) {
            float4 vf0 = *(float4*)&Vs[(n + 0) * 68 + tx * 4];
            float4 vf1 = *(float4*)&Vs[(n + 1) * 68 + tx * 4];
            float4 vf2 = *(float4*)&Vs[(n + 2) * 68 + tx * 4];
            float4 vf3 = *(float4*)&Vs[(n + 3) * 68 + tx * 4];
            #pragma unroll
            for (int r = 0; r < 8; r++) {
                float4 pf = *(float4*)&Ps[(ty * 8 + r) * 68 + n];
                O[r][0] += pf.x * vf0.x + pf.y * vf1.x + pf.z * vf2.x + pf.w * vf3.x;
                O[r][1] += pf.x * vf0.y + pf.y * vf1.y + pf.z * vf2.y + pf.w * vf3.y;
                O[r][2] += pf.x * vf0.z + pf.y * vf1.z + pf.z * vf2.z + pf.w * vf3.z;
                O[r][3] += pf.x * vf0.w + pf.y * vf1.w + pf.z * vf2.w + pf.w * vf3.w;
            }
        }
    }

    #pragma unroll
    for (int r = 0; r < 8; r++) {
        float inv = 1.f / lrow[r];
        *(float4*)&g_o1[(size_t)(b * NN + m0 + ty * 8 + r) * 64 + tx * 4] =
            make_float4(O[r][0] * inv, O[r][1] * inv, O[r][2] * inv, O[r][3] * inv);
    }
}

// =====================================================================
// K4: channel attention scores s2[c][d] = sum_n q2[n,c]*k2[n,d]
// =====================================================================
__global__ void k_zero() {
    int i = blockIdx.x * 256 + threadIdx.x;
    if (i < Bb * 4096) g_s2[i] = 0.f;
}

__global__ void k_chscore() {
    __shared__ float Qs[64][68];
    __shared__ float Ks[64][68];
    int b  = blockIdx.y;
    int n0 = blockIdx.x * 64;
    int tid = threadIdx.x;
    int cg = tid & 15, r0 = tid >> 4;
    for (int rr = r0; rr < 64; rr += 16) {
        *(float4*)&Qs[rr][cg * 4] =
            *(const float4*)&g_q2[(size_t)(b * NN + n0 + rr) * 64 + cg * 4];
        *(float4*)&Ks[rr][cg * 4] =
            *(const float4*)&g_k2[(size_t)(b * NN + n0 + rr) * 64 + cg * 4];
    }
    __syncthreads();
    int tx = tid & 15, ty = tid >> 4;   // ty -> c group, tx -> d group
    float acc[4][4] = {};
    #pragma unroll 4
    for (int n = 0; n < 64; n++) {
        float4 qf = *(float4*)&Qs[n][ty * 4];
        float4 kf = *(float4*)&Ks[n][tx * 4];
        float qa[4] = {qf.x, qf.y, qf.z, qf.w};
        float ka[4] = {kf.x, kf.y, kf.z, kf.w};
        #pragma unroll
        for (int i = 0; i < 4; i++)
            #pragma unroll
            for (int j = 0; j < 4; j++)
                acc[i][j] += qa[i] * ka[j];
    }
    #pragma unroll
    for (int i = 0; i < 4; i++)
        #pragma unroll
        for (int j = 0; j < 4; j++)
            atomicAdd(&g_s2[b * 4096 + (ty * 4 + i) * 64 + tx * 4 + j], acc[i][j]);
}

// softmax over d + M = w1_right @ softmax.  grid: b=4, block 256
__global__ void k_chsoftmax_M(const float* __restrict__ w1) {
    __shared__ float qn[64][65];
    int b = blockIdx.x;
    int tid = threadIdx.x;
    int w = tid >> 5, lane = tid & 31;
    for (int r = w; r < 64; r += 8) {
        float v0 = g_s2[b * 4096 + r * 64 + lane];
        float v1 = g_s2[b * 4096 + r * 64 + 32 + lane];
        float m = fmaxf(v0, v1);
        #pragma unroll
        for (int off = 16; off; off >>= 1)
            m = fmaxf(m, __shfl_xor_sync(0xffffffffu, m, off));
        float e0 = __expf(v0 - m), e1 = __expf(v1 - m);
        float s = e0 + e1;
        #pragma unroll
        for (int off = 16; off; off >>= 1)
            s += __shfl_xor_sync(0xffffffffu, s, off);
        float inv = 1.f / s;
        qn[r][lane] = e0 * inv;
        qn[r][lane + 32] = e1 * inv;
    }
    __syncthreads();
    int tx = tid & 15, ty = tid >> 4;   // ty -> o group, tx -> d group
    float acc[4][4] = {};
    #pragma unroll 4
    for (int c = 0; c < 64; c++) {
        float wv[4], qv[4];
        #pragma unroll
        for (int i = 0; i < 4; i++) wv[i] = w1[(ty * 4 + i) * 128 + 64 + c];
        #pragma unroll
        for (int j = 0; j < 4; j++) qv[j] = qn[c][tx * 4 + j];
        #pragma unroll
        for (int i = 0; i < 4; i++)
            #pragma unroll
            for (int j = 0; j < 4; j++)
                acc[i][j] += wv[i] * qv[j];
    }
    #pragma unroll
    for (int i = 0; i < 4; i++)
        #pragma unroll
        for (int j = 0; j < 4; j++)
            g_M[b * 4096 + (ty * 4 + i) * 64 + tx * 4 + j] = acc[i][j];
}

// =====================================================================
// K5: y = w1_left @ out1 + M @ v + b1.  grid (ptile=64, b=4)
// =====================================================================
__global__ void k_proj(const float* __restrict__ w1, const float* __restrict__ b1) {
    __shared__ float As[64][68];
    __shared__ float Ws[64][65];
    int b  = blockIdx.y;
    int p0 = blockIdx.x * 64;
    int tid = threadIdx.x;
    int tx = tid & 15, ty = tid >> 4;
    float acc[4][4] = {};

    for (int ph = 0; ph < 2; ph++) {
        __syncthreads();
        int cg = tid & 15, r0 = tid >> 4;
        for (int rr = r0; rr < 64; rr += 16) {
            float4 av, wv;
            if (ph == 0) {
                av = *(const float4*)&g_o1[(size_t)(b * NN + p0 + rr) * 64 + cg * 4];
                wv = *(const float4*)&w1[rr * 128 + cg * 4];
            } else {
                av = *(const float4*)&g_v[(size_t)(b * NN + p0 + rr) * 64 + cg * 4];
                wv = *(const float4*)&g_M[b * 4096 + rr * 64 + cg * 4];
            }
            *(float4*)&As[rr][cg * 4] = av;
            Ws[rr][cg * 4 + 0] = wv.x; Ws[rr][cg * 4 + 1] = wv.y;
            Ws[rr][cg * 4 + 2] = wv.z; Ws[rr][cg * 4 + 3] = wv.w;
        }
        __syncthreads();
        #pragma unroll 8
        for (int c = 0; c < 64; c++) {
            float a[4], wv[4];
            #pragma unroll
            for (int i = 0; i < 4; i++) a[i]  = As[ty * 4 + i][c];
            #pragma unroll
            for (int j = 0; j < 4; j++) wv[j] = Ws[tx * 4 + j][c];
            #pragma unroll
            for (int i = 0; i < 4; i++)
                #pragma unroll
                for (int j = 0; j < 4; j++)
                    acc[i][j] += a[i] * wv[j];
        }
    }
    #pragma unroll
    for (int i = 0; i < 4; i++) {
        float4 o;
        o.x = acc[i][0] + b1[tx * 4 + 0];
        o.y = acc[i][1] + b1[tx * 4 + 1];
        o.z = acc[i][2] + b1[tx * 4 + 2];
        o.w = acc[i][3] + b1[tx * 4 + 3];
        *(float4*)&g_y[(size_t)(b * NN + p0 + ty * 4 + i) * 64 + tx * 4] = o;
    }
}

// =====================================================================
// K6: bilinear 2x upsample (half-pixel centers, edge clamp) + residual
// =====================================================================
__global__ void k_upsample(const float* __restrict__ x, float* __restrict__ out) {
    int idx = blockIdx.x * 256 + threadIdx.x;
    if (idx >= Bb * Cc * HH * WW) return;
    int j = idx & 127;
    int i = (idx >> 7) & 127;
    int c = (idx >> 14) & 63;
    int b = idx >> 20;
    int p = i >> 1, q = j >> 1;
    int r0, r1; float wy0, wy1;
    if (i & 1) { r0 = p; r1 = (p + 1 < 64) ? p + 1 : 63; wy0 = 0.75f; wy1 = 0.25f; }
    else       { r0 = (p > 0) ? p - 1 : 0; r1 = p;       wy0 = 0.25f; wy1 = 0.75f; }
    int s0, s1; float wx0, wx1;
    if (j & 1) { s0 = q; s1 = (q + 1 < 64) ? q + 1 : 63; wx0 = 0.75f; wx1 = 0.25f; }
    else       { s0 = (q > 0) ? q - 1 : 0; s1 = q;       wx0 = 0.25f; wx1 = 0.75f; }
    const float* yb = g_y + (size_t)b * NN * 64;
    float v = wy0 * (wx0 * yb[(r0 * 64 + s0) * 64 + c] + wx1 * yb[(r0 * 64 + s1) * 64 + c])
            + wy1 * (wx0 * yb[(r1 * 64 + s0) * 64 + c] + wx1 * yb[(r1 * 64 + s1) * 64 + c]);
    out[idx] = v + x[idx];
}

// =====================================================================
extern "C" void kernel_launch(void* const* d_in, const int* in_sizes, int n_in,
                              void* d_out, int out_size) {
    const float* x        = (const float*)d_in[0];
    const float* pm_gamma = (const float*)d_in[1];
    const float* pm_beta  = (const float*)d_in[2];
    const float* pm_w     = (const float*)d_in[3];
    const float* pm_b     = (const float*)d_in[4];
    const float* w2 = (const float*)d_in[5];
    const float* b2 = (const float*)d_in[6];
    const float* w3 = (const float*)d_in[7];
    const float* b3 = (const float*)d_in[8];
    const float* w4 = (const float*)d_in[9];
    const float* b4 = (const float*)d_in[10];
    const float* w5 = (const float*)d_in[11];
    const float* b5 = (const float*)d_in[12];
    const float* w6 = (const float*)d_in[13];
    const float* b6 = (const float*)d_in[14];
    const float* w1 = (const float*)d_in[15];
    const float* b1 = (const float*)d_in[16];
    float* out = (float*)d_out;

    const int attn_smem = (128 * 68 + 64 * 68 + 64 * 68 + 128 * 68) * 4;  // 104448 B
    cudaFuncSetAttribute(k_attn1, cudaFuncAttributeMaxDynamicSharedMemorySize, attn_smem);

    k_merge_ln   <<<dim3(2, 64, Bb), 256>>>(x, pm_gamma, pm_beta);
    k_pmlinear   <<<dim3(64, Bb),    256>>>(pm_w, pm_b);
    k_qkv        <<<dim3(64, Bb, 5), 256>>>(w2, b2, w3, b3, w4, b4, w5, b5, w6, b6);
    k_zero       <<<64, 256>>>();
    k_attn1      <<<dim3(32, Bb), 256, attn_smem>>>();
    k_chscore    <<<dim3(64, Bb), 256>>>();
    k_chsoftmax_M<<<Bb, 256>>>(w1);
    k_proj       <<<dim3(64, Bb), 256>>>(w1, b1);
    k_upsample   <<<(Bb * Cc * HH * WW) / 256, 256>>>(x, out);
}

// round 7
// speedup vs baseline: 2.3077x; 2.2996x over previous
#include <cuda_runtime.h>

#define Bb 4
#define Cc 64
#define NN 4096    // 64*64 merged positions
#define HH 128
#define WW 128

// -------- scratch (static device globals; no allocations allowed) --------
__device__ float g_tn[Bb*NN*256];   // normalized merged features (B,N,256)
__device__ float g_c1[Bb*NN*Cc];    // (B,N,64)
__device__ float g_q [Bb*NN*Cc];
__device__ float g_k [Bb*NN*Cc];
__device__ float g_v [Bb*NN*Cc];
__device__ float g_q2[Bb*NN*Cc];
__device__ float g_k2[Bb*NN*Cc];
__device__ float g_o1[Bb*NN*Cc];    // attention-1 output (B,N,64)
__device__ float g_y [Bb*NN*Cc];    // pre-upsample output (B,N,64)
__device__ float g_s2[Bb*64*64];    // channel-attn raw scores
__device__ float g_M [Bb*64*64];    // w1_right @ softmax(scores)

// =====================================================================
// K1a: patch-merge (space-to-depth 2x2) + LayerNorm over 256 channels
// =====================================================================
__global__ void k_merge_ln(const float* __restrict__ x,
                           const float* __restrict__ gamma,
                           const float* __restrict__ beta) {
    __shared__ float ts[256][33];
    __shared__ float s_mu[32], s_rs[32];
    int b    = blockIdx.z;
    int hh   = blockIdx.y;
    int half = blockIdx.x;
    int tid  = threadIdx.x;

    for (int e = tid; e < 256 * 32; e += 256) {
        int c = e >> 5;
        int p = e & 31;
        int ww = half * 32 + p;
        int qd = c >> 6, ch = c & 63;
        int dr = qd & 1, dc = (qd >> 1) & 1;
        ts[c][p] = x[(((b * 64 + ch) * 128) + 2 * hh + dr) * 128 + 2 * ww + dc];
    }
    __syncthreads();

    int w = tid >> 5, lane = tid & 31;
    for (int p = w * 4; p < w * 4 + 4; p++) {
        float s = 0.f, ss = 0.f;
        for (int c = lane; c < 256; c += 32) {
            float v = ts[c][p];
            s += v; ss += v * v;
        }
        #pragma unroll
        for (int off = 16; off; off >>= 1) {
            s  += __shfl_xor_sync(0xffffffffu, s,  off);
            ss += __shfl_xor_sync(0xffffffffu, ss, off);
        }
        float mu  = s * (1.f / 256.f);
        float var = ss * (1.f / 256.f) - mu * mu;
        if (lane == 0) { s_mu[p] = mu; s_rs[p] = rsqrtf(var + 1e-5f); }
    }
    __syncthreads();

    int n0 = hh * 64 + half * 32;
    for (int e = tid; e < 32 * 256; e += 256) {
        int p = e >> 8;
        int c = e & 255;
        float v = (ts[c][p] - s_mu[p]) * s_rs[p] * gamma[c] + beta[c];
        g_tn[(size_t)(b * NN + n0 + p) * 256 + c] = v;
    }
}

// =====================================================================
// K1b: c1 = tn @ pm_w^T + pm_b
// =====================================================================
__global__ void k_pmlinear(const float* __restrict__ pm_w,
                           const float* __restrict__ pm_b) {
    __shared__ float As[64][68];
    __shared__ float Ws[64][65];
    int b  = blockIdx.y;
    int p0 = blockIdx.x * 64;
    int tid = threadIdx.x;
    int tx = tid & 15, ty = tid >> 4;
    float acc[4][4] = {};

    for (int kc = 0; kc < 4; kc++) {
        __syncthreads();
        int cg = tid & 15, r0 = tid >> 4;
        for (int rr = r0; rr < 64; rr += 16) {
            float4 av = *(const float4*)&g_tn[(size_t)(b * NN + p0 + rr) * 256 + kc * 64 + cg * 4];
            *(float4*)&As[rr][cg * 4] = av;
            float4 wv = *(const float4*)&pm_w[rr * 256 + kc * 64 + cg * 4];
            Ws[rr][cg * 4 + 0] = wv.x; Ws[rr][cg * 4 + 1] = wv.y;
            Ws[rr][cg * 4 + 2] = wv.z; Ws[rr][cg * 4 + 3] = wv.w;
        }
        __syncthreads();
        #pragma unroll 8
        for (int c = 0; c < 64; c++) {
            float a[4], wv[4];
            #pragma unroll
            for (int i = 0; i < 4; i++) a[i]  = As[ty * 4 + i][c];
            #pragma unroll
            for (int j = 0; j < 4; j++) wv[j] = Ws[tx * 4 + j][c];
            #pragma unroll
            for (int i = 0; i < 4; i++)
                #pragma unroll
                for (int j = 0; j < 4; j++)
                    acc[i][j] += a[i] * wv[j];
        }
    }
    #pragma unroll
    for (int i = 0; i < 4; i++) {
        float4 o;
        o.x = acc[i][0] + pm_b[tx * 4 + 0];
        o.y = acc[i][1] + pm_b[tx * 4 + 1];
        o.z = acc[i][2] + pm_b[tx * 4 + 2];
        o.w = acc[i][3] + pm_b[tx * 4 + 3];
        *(float4*)&g_c1[(size_t)(b * NN + p0 + ty * 4 + i) * 64 + tx * 4] = o;
    }
}

// =====================================================================
// K2: 5 projections q,k,v,q2,k2 = c1 @ wX^T + bX
// =====================================================================
__global__ void k_qkv(const float* w2, const float* b2,
                      const float* w3, const float* b3,
                      const float* w4, const float* b4,
                      const float* w5, const float* b5,
                      const float* w6, const float* b6) {
    __shared__ float As[64][68];
    __shared__ float Ws[64][65];
    int b  = blockIdx.y;
    int p0 = blockIdx.x * 64;
    int wi = blockIdx.z;
    const float* wp; const float* bp; float* outp;
    switch (wi) {
        case 0: wp = w2; bp = b2; outp = g_q;  break;
        case 1: wp = w3; bp = b3; outp = g_k;  break;
        case 2: wp = w4; bp = b4; outp = g_v;  break;
        case 3: wp = w5; bp = b5; outp = g_q2; break;
        default: wp = w6; bp = b6; outp = g_k2; break;
    }
    int tid = threadIdx.x;
    int tx = tid & 15, ty = tid >> 4;
    int cg = tid & 15, r0 = tid >> 4;
    for (int rr = r0; rr < 64; rr += 16) {
        float4 av = *(const float4*)&g_c1[(size_t)(b * NN + p0 + rr) * 64 + cg * 4];
        *(float4*)&As[rr][cg * 4] = av;
        float4 wv = *(const float4*)&wp[rr * 64 + cg * 4];
        Ws[rr][cg * 4 + 0] = wv.x; Ws[rr][cg * 4 + 1] = wv.y;
        Ws[rr][cg * 4 + 2] = wv.z; Ws[rr][cg * 4 + 3] = wv.w;
    }
    __syncthreads();
    float acc[4][4] = {};
    #pragma unroll 8
    for (int c = 0; c < 64; c++) {
        float a[4], wv[4];
        #pragma unroll
        for (int i = 0; i < 4; i++) a[i]  = As[ty * 4 + i][c];
        #pragma unroll
        for (int j = 0; j < 4; j++) wv[j] = Ws[tx * 4 + j][c];
        #pragma unroll
        for (int i = 0; i < 4; i++)
            #pragma unroll
            for (int j = 0; j < 4; j++)
                acc[i][j] += a[i] * wv[j];
    }
    #pragma unroll
    for (int i = 0; i < 4; i++) {
        float4 o;
        o.x = acc[i][0] + bp[tx * 4 + 0];
        o.y = acc[i][1] + bp[tx * 4 + 1];
        o.z = acc[i][2] + bp[tx * 4 + 2];
        o.w = acc[i][3] + bp[tx * 4 + 3];
        *(float4*)&outp[(size_t)(b * NN + p0 + ty * 4 + i) * 64 + tx * 4] = o;
    }
}

// =====================================================================
// K3: flash attention 1 with tf32 tensor-core mma (m16n8k8).
// BM=128, BN=64, d=64, 8 warps; each warp owns 16 rows.
// Smem strides chosen for conflict-free fragment LDS:
//   Ks[n][k] stride 68  (b0 banks 4g+t  -> 32 distinct)
//   Vs[p][c] stride 72  (b0 banks 8t+g  -> 32 distinct)
//   Pw[r][k] stride 68  (a0 banks 4r+t  -> 32 distinct)
// =====================================================================
__device__ __forceinline__ unsigned f2tf(float f) {
    unsigned u;
    asm("cvt.rna.tf32.f32 %0, %1;" : "=r"(u) : "f"(f));
    return u;
}

__device__ __forceinline__ void mma_tf32(float c[4],
                                         const unsigned a[4],
                                         unsigned b0, unsigned b1) {
    asm volatile(
        "mma.sync.aligned.m16n8k8.row.col.f32.tf32.tf32.f32 "
        "{%0,%1,%2,%3}, {%4,%5,%6,%7}, {%8,%9}, {%0,%1,%2,%3};"
        : "+f"(c[0]), "+f"(c[1]), "+f"(c[2]), "+f"(c[3])
        : "r"(a[0]), "r"(a[1]), "r"(a[2]), "r"(a[3]), "r"(b0), "r"(b1));
}

#define SK 68
#define SV 72
#define SP 68

extern __shared__ float smem3[];
__global__ void __launch_bounds__(256, 1) k_attn1_tc() {
    unsigned* Ks = (unsigned*)smem3;           // [64][SK]
    unsigned* Vs = Ks + 64 * SK;               // [64][SV]
    unsigned* Pw = Vs + 64 * SV;               // 8 warps * [16][SP] (= Q staging 128*SK)

    int b   = blockIdx.y;
    int m0  = blockIdx.x * 128;
    int tid = threadIdx.x;
    int w   = tid >> 5, lane = tid & 31;
    int g   = lane >> 2, t = lane & 3;
    int cg  = tid & 15, r0 = tid >> 4;

    const float* Qg = g_q + (size_t)(b * NN + m0) * 64;
    const float* Kg = g_k + (size_t)b * NN * 64;
    const float* Vg = g_v + (size_t)b * NN * 64;

    // ---- stage Q (tf32) into Pw region, extract A fragments ----
    for (int r = r0; r < 128; r += 16) {
        float4 q = *(const float4*)&Qg[r * 64 + cg * 4];
        unsigned* d = &Pw[r * SK + cg * 4];
        d[0] = f2tf(q.x); d[1] = f2tf(q.y); d[2] = f2tf(q.z); d[3] = f2tf(q.w);
    }
    __syncthreads();
    unsigned qf[8][4];
    {
        int rA = w * 16 + g;
        #pragma unroll
        for (int a = 0; a < 8; a++) {
            qf[a][0] = Pw[rA * SK + 8 * a + t];
            qf[a][1] = Pw[(rA + 8) * SK + 8 * a + t];
            qf[a][2] = Pw[rA * SK + 8 * a + t + 4];
            qf[a][3] = Pw[(rA + 8) * SK + 8 * a + t + 4];
        }
    }
    __syncthreads();

    unsigned* Pme = Pw + w * 16 * SP;   // this warp's P region

    float O[8][4] = {};
    float m1 = -1e30f, m2 = -1e30f, l1 = 0.f, l2 = 0.f;

    // prefetch first K/V tile
    float4 pk[4], pv[4];
    #pragma unroll
    for (int i = 0; i < 4; i++) {
        int r = r0 + 16 * i;
        pk[i] = *(const float4*)&Kg[(size_t)r * 64 + cg * 4];
        pv[i] = *(const float4*)&Vg[(size_t)r * 64 + cg * 4];
    }

    for (int n0 = 0; n0 < NN; n0 += 64) {
        // store prefetched tile (tf32)
        #pragma unroll
        for (int i = 0; i < 4; i++) {
            int r = r0 + 16 * i;
            unsigned* dk = &Ks[r * SK + cg * 4];
            dk[0] = f2tf(pk[i].x); dk[1] = f2tf(pk[i].y);
            dk[2] = f2tf(pk[i].z); dk[3] = f2tf(pk[i].w);
            unsigned* dv = &Vs[r * SV + cg * 4];
            dv[0] = f2tf(pv[i].x); dv[1] = f2tf(pv[i].y);
            dv[2] = f2tf(pv[i].z); dv[3] = f2tf(pv[i].w);
        }
        __syncthreads();

        // prefetch next tile (overlaps with compute)
        if (n0 + 64 < NN) {
            #pragma unroll
            for (int i = 0; i < 4; i++) {
                int r = n0 + 64 + r0 + 16 * i;
                pk[i] = *(const float4*)&Kg[(size_t)r * 64 + cg * 4];
                pv[i] = *(const float4*)&Vg[(size_t)r * 64 + cg * 4];
            }
        }

        // ---- S = Q K^T ----
        float S[8][4] = {};
        #pragma unroll
        for (int ka = 0; ka < 8; ka++) {
            #pragma unroll
            for (int na = 0; na < 8; na++) {
                unsigned b0 = Ks[(8 * na + g) * SK + 8 * ka + t];
                unsigned b1 = Ks[(8 * na + g) * SK + 8 * ka + t + 4];
                mma_tf32(S[na], qf[ka], b0, b1);
            }
        }

        // ---- online softmax (rows r1=g, r2=g+8 of this warp's 16) ----
        float tm1 = -1e30f, tm2 = -1e30f;
        #pragma unroll
        for (int na = 0; na < 8; na++) {
            tm1 = fmaxf(tm1, fmaxf(S[na][0], S[na][1]));
            tm2 = fmaxf(tm2, fmaxf(S[na][2], S[na][3]));
        }
        tm1 = fmaxf(tm1, __shfl_xor_sync(0xffffffffu, tm1, 1));
        tm1 = fmaxf(tm1, __shfl_xor_sync(0xffffffffu, tm1, 2));
        tm2 = fmaxf(tm2, __shfl_xor_sync(0xffffffffu, tm2, 1));
        tm2 = fmaxf(tm2, __shfl_xor_sync(0xffffffffu, tm2, 2));

        float mn1 = fmaxf(m1, tm1), mn2 = fmaxf(m2, tm2);
        float a1 = __expf(m1 - mn1), a2 = __expf(m2 - mn2);
        m1 = mn1; m2 = mn2;

        float rs1 = 0.f, rs2 = 0.f;
        #pragma unroll
        for (int na = 0; na < 8; na++) {
            float p0 = __expf(S[na][0] - mn1);
            float p1 = __expf(S[na][1] - mn1);
            float p2 = __expf(S[na][2] - mn2);
            float p3 = __expf(S[na][3] - mn2);
            rs1 += p0 + p1; rs2 += p2 + p3;
            Pme[g * SP + 8 * na + 2 * t]           = f2tf(p0);
            Pme[g * SP + 8 * na + 2 * t + 1]       = f2tf(p1);
            Pme[(g + 8) * SP + 8 * na + 2 * t]     = f2tf(p2);
            Pme[(g + 8) * SP + 8 * na + 2 * t + 1] = f2tf(p3);
        }
        rs1 += __shfl_xor_sync(0xffffffffu, rs1, 1);
        rs1 += __shfl_xor_sync(0xffffffffu, rs1, 2);
        rs2 += __shfl_xor_sync(0xffffffffu, rs2, 1);
        rs2 += __shfl_xor_sync(0xffffffffu, rs2, 2);
        l1 = l1 * a1 + rs1;
        l2 = l2 * a2 + rs2;
        #pragma unroll
        for (int na = 0; na < 8; na++) {
            O[na][0] *= a1; O[na][1] *= a1;
            O[na][2] *= a2; O[na][3] *= a2;
        }
        __syncwarp();

        // ---- O += P V ----
        #pragma unroll
        for (int ka = 0; ka < 8; ka++) {
            unsigned pa[4];
            pa[0] = Pme[g * SP + 8 * ka + t];
            pa[1] = Pme[(g + 8) * SP + 8 * ka + t];
            pa[2] = Pme[g * SP + 8 * ka + t + 4];
            pa[3] = Pme[(g + 8) * SP + 8 * ka + t + 4];
            #pragma unroll
            for (int na = 0; na < 8; na++) {
                unsigned b0 = Vs[(8 * ka + t) * SV + 8 * na + g];
                unsigned b1 = Vs[(8 * ka + t + 4) * SV + 8 * na + g];
                mma_tf32(O[na], pa, b0, b1);
            }
        }
        __syncthreads();
    }

    float i1 = 1.f / l1, i2 = 1.f / l2;
    int row1 = m0 + w * 16 + g, row2 = row1 + 8;
    #pragma unroll
    for (int na = 0; na < 8; na++) {
        *(float2*)&g_o1[(size_t)(b * NN + row1) * 64 + 8 * na + 2 * t] =
            make_float2(O[na][0] * i1, O[na][1] * i1);
        *(float2*)&g_o1[(size_t)(b * NN + row2) * 64 + 8 * na + 2 * t] =
            make_float2(O[na][2] * i2, O[na][3] * i2);
    }
}

// =====================================================================
// K4: channel attention
// =====================================================================
__global__ void k_zero() {
    int i = blockIdx.x * 256 + threadIdx.x;
    if (i < Bb * 4096) g_s2[i] = 0.f;
}

__global__ void k_chscore() {
    __shared__ float Qs[64][68];
    __shared__ float Ksm[64][68];
    int b  = blockIdx.y;
    int n0 = blockIdx.x * 64;
    int tid = threadIdx.x;
    int cg = tid & 15, r0 = tid >> 4;
    for (int rr = r0; rr < 64; rr += 16) {
        *(float4*)&Qs[rr][cg * 4] =
            *(const float4*)&g_q2[(size_t)(b * NN + n0 + rr) * 64 + cg * 4];
        *(float4*)&Ksm[rr][cg * 4] =
            *(const float4*)&g_k2[(size_t)(b * NN + n0 + rr) * 64 + cg * 4];
    }
    __syncthreads();
    int tx = tid & 15, ty = tid >> 4;
    float acc[4][4] = {};
    #pragma unroll 4
    for (int n = 0; n < 64; n++) {
        float4 qf = *(float4*)&Qs[n][ty * 4];
        float4 kf = *(float4*)&Ksm[n][tx * 4];
        float qa[4] = {qf.x, qf.y, qf.z, qf.w};
        float ka[4] = {kf.x, kf.y, kf.z, kf.w};
        #pragma unroll
        for (int i = 0; i < 4; i++)
            #pragma unroll
            for (int j = 0; j < 4; j++)
                acc[i][j] += qa[i] * ka[j];
    }
    #pragma unroll
    for (int i = 0; i < 4; i++)
        #pragma unroll
        for (int j = 0; j < 4; j++)
            atomicAdd(&g_s2[b * 4096 + (ty * 4 + i) * 64 + tx * 4 + j], acc[i][j]);
}

__global__ void k_chsoftmax_M(const float* __restrict__ w1) {
    __shared__ float qn[64][65];
    int b = blockIdx.x;
    int tid = threadIdx.x;
    int w = tid >> 5, lane = tid & 31;
    for (int r = w; r < 64; r += 8) {
        float v0 = g_s2[b * 4096 + r * 64 + lane];
        float v1 = g_s2[b * 4096 + r * 64 + 32 + lane];
        float m = fmaxf(v0, v1);
        #pragma unroll
        for (int off = 16; off; off >>= 1)
            m = fmaxf(m, __shfl_xor_sync(0xffffffffu, m, off));
        float e0 = __expf(v0 - m), e1 = __expf(v1 - m);
        float s = e0 + e1;
        #pragma unroll
        for (int off = 16; off; off >>= 1)
            s += __shfl_xor_sync(0xffffffffu, s, off);
        float inv = 1.f / s;
        qn[r][lane] = e0 * inv;
        qn[r][lane + 32] = e1 * inv;
    }
    __syncthreads();
    int tx = tid & 15, ty = tid >> 4;
    float acc[4][4] = {};
    #pragma unroll 4
    for (int c = 0; c < 64; c++) {
        float wv[4], qv[4];
        #pragma unroll
        for (int i = 0; i < 4; i++) wv[i] = w1[(ty * 4 + i) * 128 + 64 + c];
        #pragma unroll
        for (int j = 0; j < 4; j++) qv[j] = qn[c][tx * 4 + j];
        #pragma unroll
        for (int i = 0; i < 4; i++)
            #pragma unroll
            for (int j = 0; j < 4; j++)
                acc[i][j] += wv[i] * qv[j];
    }
    #pragma unroll
    for (int i = 0; i < 4; i++)
        #pragma unroll
        for (int j = 0; j < 4; j++)
            g_M[b * 4096 + (ty * 4 + i) * 64 + tx * 4 + j] = acc[i][j];
}

// =====================================================================
// K5: y = w1_left @ out1 + M @ v + b1
// =====================================================================
__global__ void k_proj(const float* __restrict__ w1, const float* __restrict__ b1) {
    __shared__ float As[64][68];
    __shared__ float Ws[64][65];
    int b  = blockIdx.y;
    int p0 = blockIdx.x * 64;
    int tid = threadIdx.x;
    int tx = tid & 15, ty = tid >> 4;
    float acc[4][4] = {};

    for (int ph = 0; ph < 2; ph++) {
        __syncthreads();
        int cg = tid & 15, r0 = tid >> 4;
        for (int rr = r0; rr < 64; rr += 16) {
            float4 av, wv;
            if (ph == 0) {
                av = *(const float4*)&g_o1[(size_t)(b * NN + p0 + rr) * 64 + cg * 4];
                wv = *(const float4*)&w1[rr * 128 + cg * 4];
            } else {
                av = *(const float4*)&g_v[(size_t)(b * NN + p0 + rr) * 64 + cg * 4];
                wv = *(const float4*)&g_M[b * 4096 + rr * 64 + cg * 4];
            }
            *(float4*)&As[rr][cg * 4] = av;
            Ws[rr][cg * 4 + 0] = wv.x; Ws[rr][cg * 4 + 1] = wv.y;
            Ws[rr][cg * 4 + 2] = wv.z; Ws[rr][cg * 4 + 3] = wv.w;
        }
        __syncthreads();
        #pragma unroll 8
        for (int c = 0; c < 64; c++) {
            float a[4], wv[4];
            #pragma unroll
            for (int i = 0; i < 4; i++) a[i]  = As[ty * 4 + i][c];
            #pragma unroll
            for (int j = 0; j < 4; j++) wv[j] = Ws[tx * 4 + j][c];
            #pragma unroll
            for (int i = 0; i < 4; i++)
                #pragma unroll
                for (int j = 0; j < 4; j++)
                    acc[i][j] += a[i] * wv[j];
        }
    }
    #pragma unroll
    for (int i = 0; i < 4; i++) {
        float4 o;
        o.x = acc[i][0] + b1[tx * 4 + 0];
        o.y = acc[i][1] + b1[tx * 4 + 1];
        o.z = acc[i][2] + b1[tx * 4 + 2];
        o.w = acc[i][3] + b1[tx * 4 + 3];
        *(float4*)&g_y[(size_t)(b * NN + p0 + ty * 4 + i) * 64 + tx * 4] = o;
    }
}

// =====================================================================
// K6: bilinear 2x upsample + residual
// =====================================================================
__global__ void k_upsample(const float* __restrict__ x, float* __restrict__ out) {
    int idx = blockIdx.x * 256 + threadIdx.x;
    if (idx >= Bb * Cc * HH * WW) return;
    int j = idx & 127;
    int i = (idx >> 7) & 127;
    int c = (idx >> 14) & 63;
    int b = idx >> 20;
    int p = i >> 1, q = j >> 1;
    int r0, r1; float wy0, wy1;
    if (i & 1) { r0 = p; r1 = (p + 1 < 64) ? p + 1 : 63; wy0 = 0.75f; wy1 = 0.25f; }
    else       { r0 = (p > 0) ? p - 1 : 0; r1 = p;       wy0 = 0.25f; wy1 = 0.75f; }
    int s0, s1; float wx0, wx1;
    if (j & 1) { s0 = q; s1 = (q + 1 < 64) ? q + 1 : 63; wx0 = 0.75f; wx1 = 0.25f; }
    else       { s0 = (q > 0) ? q - 1 : 0; s1 = q;       wx0 = 0.25f; wx1 = 0.75f; }
    const float* yb = g_y + (size_t)b * NN * 64;
    float v = wy0 * (wx0 * yb[(r0 * 64 + s0) * 64 + c] + wx1 * yb[(r0 * 64 + s1) * 64 + c])
            + wy1 * (wx0 * yb[(r1 * 64 + s0) * 64 + c] + wx1 * yb[(r1 * 64 + s1) * 64 + c]);
    out[idx] = v + x[idx];
}

// =====================================================================
extern "C" void kernel_launch(void* const* d_in, const int* in_sizes, int n_in,
                              void* d_out, int out_size) {
    const float* x        = (const float*)d_in[0];
    const float* pm_gamma = (const float*)d_in[1];
    const float* pm_beta  = (const float*)d_in[2];
    const float* pm_w     = (const float*)d_in[3];
    const float* pm_b     = (const float*)d_in[4];
    const float* w2 = (const float*)d_in[5];
    const float* b2 = (const float*)d_in[6];
    const float* w3 = (const float*)d_in[7];
    const float* b3 = (const float*)d_in[8];
    const float* w4 = (const float*)d_in[9];
    const float* b4 = (const float*)d_in[10];
    const float* w5 = (const float*)d_in[11];
    const float* b5 = (const float*)d_in[12];
    const float* w6 = (const float*)d_in[13];
    const float* b6 = (const float*)d_in[14];
    const float* w1 = (const float*)d_in[15];
    const float* b1 = (const float*)d_in[16];
    float* out = (float*)d_out;

    const int attn_smem = (64 * SK + 64 * SV + 128 * SP) * 4;  // 70656 B
    cudaFuncSetAttribute(k_attn1_tc, cudaFuncAttributeMaxDynamicSharedMemorySize, attn_smem);

    k_merge_ln   <<<dim3(2, 64, Bb), 256>>>(x, pm_gamma, pm_beta);
    k_pmlinear   <<<dim3(64, Bb),    256>>>(pm_w, pm_b);
    k_qkv        <<<dim3(64, Bb, 5), 256>>>(w2, b2, w3, b3, w4, b4, w5, b5, w6, b6);
    k_zero       <<<64, 256>>>();
    k_attn1_tc   <<<dim3(32, Bb), 256, attn_smem>>>();
    k_chscore    <<<dim3(64, Bb), 256>>>();
    k_chsoftmax_M<<<Bb, 256>>>(w1);
    k_proj       <<<dim3(64, Bb), 256>>>(w1, b1);
    k_upsample   <<<(Bb * Cc * HH * WW) / 256, 256>>>(x, out);
}

// round 8
// speedup vs baseline: 2.5889x; 1.1219x over previous
#include <cuda_runtime.h>

#define Bb 4
#define Cc 64
#define NN 4096    // 64*64 merged positions
#define HH 128
#define WW 128

// -------- scratch (static device globals) --------
__device__ float g_c1[Bb*NN*Cc];    // (B,N,64)
__device__ float g_q [Bb*NN*Cc];
__device__ float g_k [Bb*NN*Cc];
__device__ float g_v [Bb*NN*Cc];
__device__ float g_q2[Bb*NN*Cc];
__device__ float g_k2[Bb*NN*Cc];
__device__ float g_o1[Bb*NN*Cc];    // attention-1 output (B,N,64)
__device__ float g_y [Bb*NN*Cc];    // pre-upsample output (B,N,64)
__device__ float g_s2[Bb*64*64];    // channel-attn raw scores
__device__ float g_M [Bb*64*64];    // w1_right @ softmax(scores)

__device__ __forceinline__ unsigned f2tf(float f) {
    unsigned u;
    asm("cvt.rna.tf32.f32 %0, %1;" : "=r"(u) : "f"(f));
    return u;
}

// =====================================================================
// K1: fused patch-merge + LayerNorm + pm linear (256->64)
// grid (hh=64, b=4), block 256, dynamic smem (256*65 + 64*65 floats)
// =====================================================================
extern __shared__ float smM[];
__global__ void k_merge_pml(const float* __restrict__ x,
                            const float* __restrict__ gamma,
                            const float* __restrict__ beta,
                            const float* __restrict__ pm_w,
                            const float* __restrict__ pm_b) {
    float (*ts)[65] = (float(*)[65])smM;              // [256][65]
    float (*Ws)[65] = (float(*)[65])(smM + 256 * 65); // [64][65]
    __shared__ float s_mu[64], s_rs[64];
    int b = blockIdx.y, hh = blockIdx.x, tid = threadIdx.x;

    if (hh < 16) g_s2[b * 4096 + hh * 256 + tid] = 0.f;   // zero chattn scores

    // load 2 rows of x per channel as float2 (coalesced), split even/odd col
    for (int e = tid; e < 8192; e += 256) {
        int c2 = e >> 6;      // 0..127 : dr*64 + ch
        int p  = e & 63;
        int dr = c2 >> 6;
        int ch = c2 & 63;
        float2 v = *(const float2*)&x[(((b * 64 + ch) * 128) + 2 * hh + dr) * 128 + 2 * p];
        ts[dr * 64 + ch][p]       = v.x;   // dc=0 quadrant
        ts[dr * 64 + ch + 128][p] = v.y;   // dc=1 quadrant
    }
    __syncthreads();

    // LN stats: 8 warps x 8 positions
    int w = tid >> 5, lane = tid & 31;
    for (int p = w * 8; p < w * 8 + 8; p++) {
        float s = 0.f, ss = 0.f;
        for (int c = lane; c < 256; c += 32) {
            float v = ts[c][p];
            s += v; ss += v * v;
        }
        #pragma unroll
        for (int off = 16; off; off >>= 1) {
            s  += __shfl_xor_sync(0xffffffffu, s,  off);
            ss += __shfl_xor_sync(0xffffffffu, ss, off);
        }
        float mu  = s * (1.f / 256.f);
        float var = ss * (1.f / 256.f) - mu * mu;
        if (lane == 0) { s_mu[p] = mu; s_rs[p] = rsqrtf(var + 1e-5f); }
    }
    __syncthreads();

    // normalize in place
    for (int e = tid; e < 16384; e += 256) {
        int c = e >> 6, p = e & 63;
        ts[c][p] = (ts[c][p] - s_mu[p]) * s_rs[p] * gamma[c] + beta[c];
    }

    // GEMM: out[pos][o] = sum_c ts[c][pos] * pm_w[o][c]
    int tx = tid & 15, ty = tid >> 4;
    float acc[4][4] = {};
    for (int kc = 0; kc < 4; kc++) {
        __syncthreads();
        int cg = tid & 15, r0 = tid >> 4;
        for (int rr = r0; rr < 64; rr += 16) {
            float4 wv = *(const float4*)&pm_w[rr * 256 + kc * 64 + cg * 4];
            Ws[rr][cg * 4 + 0] = wv.x; Ws[rr][cg * 4 + 1] = wv.y;
            Ws[rr][cg * 4 + 2] = wv.z; Ws[rr][cg * 4 + 3] = wv.w;
        }
        __syncthreads();
        #pragma unroll 8
        for (int c = 0; c < 64; c++) {
            float a[4], wv[4];
            #pragma unroll
            for (int i = 0; i < 4; i++) a[i]  = ts[kc * 64 + c][ty * 4 + i];
            #pragma unroll
            for (int j = 0; j < 4; j++) wv[j] = Ws[tx * 4 + j][c];
            #pragma unroll
            for (int i = 0; i < 4; i++)
                #pragma unroll
                for (int j = 0; j < 4; j++)
                    acc[i][j] += a[i] * wv[j];
        }
    }
    #pragma unroll
    for (int i = 0; i < 4; i++) {
        float4 o;
        o.x = acc[i][0] + pm_b[tx * 4 + 0];
        o.y = acc[i][1] + pm_b[tx * 4 + 1];
        o.z = acc[i][2] + pm_b[tx * 4 + 2];
        o.w = acc[i][3] + pm_b[tx * 4 + 3];
        *(float4*)&g_c1[(size_t)(b * NN + hh * 64 + ty * 4 + i) * 64 + tx * 4] = o;
    }
}

// =====================================================================
// K2: all 5 projections in one kernel (As loaded once).
// q,k,v stored pre-rounded to tf32; q2,k2 stored exact fp32.
// grid (ptile=64, b=4), block 256
// =====================================================================
__global__ void k_qkv5(const float* __restrict__ w2, const float* __restrict__ b2,
                       const float* __restrict__ w3, const float* __restrict__ b3,
                       const float* __restrict__ w4, const float* __restrict__ b4,
                       const float* __restrict__ w5, const float* __restrict__ b5,
                       const float* __restrict__ w6, const float* __restrict__ b6) {
    __shared__ float As[64][68];
    __shared__ float Ws[64][65];
    int b  = blockIdx.y;
    int p0 = blockIdx.x * 64;
    int tid = threadIdx.x;
    int tx = tid & 15, ty = tid >> 4;
    int cg = tid & 15, r0 = tid >> 4;

    for (int rr = r0; rr < 64; rr += 16)
        *(float4*)&As[rr][cg * 4] =
            *(const float4*)&g_c1[(size_t)(b * NN + p0 + rr) * 64 + cg * 4];

    const float* wps[5] = {w2, w3, w4, w5, w6};
    const float* bps[5] = {b2, b3, b4, b5, b6};
    float* outs[5] = {g_q, g_k, g_v, g_q2, g_k2};

    for (int wi = 0; wi < 5; wi++) {
        __syncthreads();
        const float* wp = wps[wi];
        for (int rr = r0; rr < 64; rr += 16) {
            float4 wv = *(const float4*)&wp[rr * 64 + cg * 4];
            Ws[rr][cg * 4 + 0] = wv.x; Ws[rr][cg * 4 + 1] = wv.y;
            Ws[rr][cg * 4 + 2] = wv.z; Ws[rr][cg * 4 + 3] = wv.w;
        }
        __syncthreads();
        float acc[4][4] = {};
        #pragma unroll 8
        for (int c = 0; c < 64; c++) {
            float a[4], wv[4];
            #pragma unroll
            for (int i = 0; i < 4; i++) a[i]  = As[ty * 4 + i][c];
            #pragma unroll
            for (int j = 0; j < 4; j++) wv[j] = Ws[tx * 4 + j][c];
            #pragma unroll
            for (int i = 0; i < 4; i++)
                #pragma unroll
                for (int j = 0; j < 4; j++)
                    acc[i][j] += a[i] * wv[j];
        }
        const float* bp = bps[wi];
        float* outp = outs[wi];
        bool rnd = (wi < 3);   // q,k,v pre-rounded to tf32
        #pragma unroll
        for (int i = 0; i < 4; i++) {
            float4 o;
            o.x = acc[i][0] + bp[tx * 4 + 0];
            o.y = acc[i][1] + bp[tx * 4 + 1];
            o.z = acc[i][2] + bp[tx * 4 + 2];
            o.w = acc[i][3] + bp[tx * 4 + 3];
            if (rnd) {
                o.x = __uint_as_float(f2tf(o.x));
                o.y = __uint_as_float(f2tf(o.y));
                o.z = __uint_as_float(f2tf(o.z));
                o.w = __uint_as_float(f2tf(o.w));
            }
            *(float4*)&outp[(size_t)(b * NN + p0 + ty * 4 + i) * 64 + tx * 4] = o;
        }
    }
}

// =====================================================================
// K3: flash attention, tf32 mma m16n8k8.
// 4 warps (128 thr), warp-m=32 (BM=128), BN=64, d=64.
// Q & O in registers; K/V double-buffered via cp.async.
// =====================================================================
__device__ __forceinline__ void mma_tf32(float c[4], const float a[4],
                                         float b0f, float b1f) {
    asm volatile(
        "mma.sync.aligned.m16n8k8.row.col.f32.tf32.tf32.f32 "
        "{%0,%1,%2,%3}, {%4,%5,%6,%7}, {%8,%9}, {%0,%1,%2,%3};"
        : "+f"(c[0]), "+f"(c[1]), "+f"(c[2]), "+f"(c[3])
        : "r"(__float_as_uint(a[0])), "r"(__float_as_uint(a[1])),
          "r"(__float_as_uint(a[2])), "r"(__float_as_uint(a[3])),
          "r"(__float_as_uint(b0f)), "r"(__float_as_uint(b1f)));
}

__device__ __forceinline__ unsigned su32(const void* p) {
    return (unsigned)__cvta_generic_to_shared(p);
}

#define SKK 68
#define SVV 72
#define SPP 68

extern __shared__ float smA[];
__global__ void __launch_bounds__(128, 1) k_attn1_tc() {
    float* Kb = smA;                      // [2][64*SKK]
    float* Vb = Kb + 2 * 64 * SKK;        // [2][64*SVV]
    float* Ps = Vb + 2 * 64 * SVV;        // [128*SPP] (Q staging, then P)

    int b   = blockIdx.y;
    int m0  = blockIdx.x * 128;
    int tid = threadIdx.x;
    int w   = tid >> 5, lane = tid & 31;
    int g   = lane >> 2, t = lane & 3;

    const float* Qg = g_q + (size_t)(b * NN + m0) * 64;
    const float* Kg = g_k + (size_t)b * NN * 64;
    const float* Vg = g_v + (size_t)b * NN * 64;

    // prologue: issue cp.async for tiles 0,1
    for (int s = 0; s < 2; s++) {
        const float* kp = Kg + s * 64 * 64;
        const float* vp = Vg + s * 64 * 64;
        float* kd = Kb + s * 64 * SKK;
        float* vd = Vb + s * 64 * SVV;
        for (int idx = tid; idx < 1024; idx += 128) {
            int r = idx >> 4, c = idx & 15;
            asm volatile("cp.async.cg.shared.global [%0], [%1], 16;" ::
                "r"(su32(kd + r * SKK + c * 4)), "l"(kp + r * 64 + c * 4));
            asm volatile("cp.async.cg.shared.global [%0], [%1], 16;" ::
                "r"(su32(vd + r * SVV + c * 4)), "l"(vp + r * 64 + c * 4));
        }
        asm volatile("cp.async.commit_group;");
    }

    // stage Q, extract A fragments (q already tf32-rounded in gmem)
    for (int idx = tid; idx < 2048; idx += 128) {
        int r = idx >> 4, c = idx & 15;
        *(float4*)&Ps[r * SPP + c * 4] = *(const float4*)&Qg[r * 64 + c * 4];
    }
    __syncthreads();
    float qf[2][8][4];
    #pragma unroll
    for (int rb = 0; rb < 2; rb++) {
        int rA = 32 * w + 16 * rb + g;
        #pragma unroll
        for (int a = 0; a < 8; a++) {
            qf[rb][a][0] = Ps[rA * SPP + 8 * a + t];
            qf[rb][a][1] = Ps[(rA + 8) * SPP + 8 * a + t];
            qf[rb][a][2] = Ps[rA * SPP + 8 * a + t + 4];
            qf[rb][a][3] = Ps[(rA + 8) * SPP + 8 * a + t + 4];
        }
    }

    float* Pme = Ps + 32 * w * SPP;   // warp's own 32-row P region

    float O[2][8][4] = {};
    float mx[2][2], ls[2][2];
    #pragma unroll
    for (int rb = 0; rb < 2; rb++) {
        mx[rb][0] = mx[rb][1] = -1e30f;
        ls[rb][0] = ls[rb][1] = 0.f;
    }

    for (int it = 0; it < 64; it++) {
        asm volatile("cp.async.wait_group 1;" ::: "memory");
        __syncthreads();
        const float* Ks = Kb + (it & 1) * 64 * SKK;
        const float* Vs = Vb + (it & 1) * 64 * SVV;

        // ---- S = Q K^T (B-fragments shared across both rowblocks) ----
        float S[2][8][4] = {};
        #pragma unroll
        for (int ka = 0; ka < 8; ka++) {
            #pragma unroll
            for (int na = 0; na < 8; na++) {
                float b0 = Ks[(8 * na + g) * SKK + 8 * ka + t];
                float b1 = Ks[(8 * na + g) * SKK + 8 * ka + t + 4];
                mma_tf32(S[0][na], qf[0][ka], b0, b1);
                mma_tf32(S[1][na], qf[1][ka], b0, b1);
            }
        }

        // ---- online softmax per rowblock ----
        #pragma unroll
        for (int rb = 0; rb < 2; rb++) {
            float tm1 = -1e30f, tm2 = -1e30f;
            #pragma unroll
            for (int na = 0; na < 8; na++) {
                tm1 = fmaxf(tm1, fmaxf(S[rb][na][0], S[rb][na][1]));
                tm2 = fmaxf(tm2, fmaxf(S[rb][na][2], S[rb][na][3]));
            }
            tm1 = fmaxf(tm1, __shfl_xor_sync(0xffffffffu, tm1, 1));
            tm1 = fmaxf(tm1, __shfl_xor_sync(0xffffffffu, tm1, 2));
            tm2 = fmaxf(tm2, __shfl_xor_sync(0xffffffffu, tm2, 1));
            tm2 = fmaxf(tm2, __shfl_xor_sync(0xffffffffu, tm2, 2));

            float mn1 = fmaxf(mx[rb][0], tm1), mn2 = fmaxf(mx[rb][1], tm2);
            float a1 = __expf(mx[rb][0] - mn1), a2 = __expf(mx[rb][1] - mn2);
            mx[rb][0] = mn1; mx[rb][1] = mn2;

            float rs1 = 0.f, rs2 = 0.f;
            int rowA = (16 * rb + g) * SPP, rowB = (16 * rb + 8 + g) * SPP;
            #pragma unroll
            for (int na = 0; na < 8; na++) {
                float p0 = __expf(S[rb][na][0] - mn1);
                float p1 = __expf(S[rb][na][1] - mn1);
                float p2 = __expf(S[rb][na][2] - mn2);
                float p3 = __expf(S[rb][na][3] - mn2);
                rs1 += p0 + p1; rs2 += p2 + p3;
                *(float2*)&Pme[rowA + 8 * na + 2 * t] =
                    make_float2(__uint_as_float(f2tf(p0)), __uint_as_float(f2tf(p1)));
                *(float2*)&Pme[rowB + 8 * na + 2 * t] =
                    make_float2(__uint_as_float(f2tf(p2)), __uint_as_float(f2tf(p3)));
            }
            rs1 += __shfl_xor_sync(0xffffffffu, rs1, 1);
            rs1 += __shfl_xor_sync(0xffffffffu, rs1, 2);
            rs2 += __shfl_xor_sync(0xffffffffu, rs2, 1);
            rs2 += __shfl_xor_sync(0xffffffffu, rs2, 2);
            ls[rb][0] = ls[rb][0] * a1 + rs1;
            ls[rb][1] = ls[rb][1] * a2 + rs2;
            #pragma unroll
            for (int na = 0; na < 8; na++) {
                O[rb][na][0] *= a1; O[rb][na][1] *= a1;
                O[rb][na][2] *= a2; O[rb][na][3] *= a2;
            }
        }
        __syncwarp();

        // ---- O += P V (B-fragments shared across both rowblocks) ----
        #pragma unroll
        for (int ka = 0; ka < 8; ka++) {
            float pa0[4], pa1[4];
            pa0[0] = Pme[g * SPP + 8 * ka + t];
            pa0[1] = Pme[(8 + g) * SPP + 8 * ka + t];
            pa0[2] = Pme[g * SPP + 8 * ka + t + 4];
            pa0[3] = Pme[(8 + g) * SPP + 8 * ka + t + 4];
            pa1[0] = Pme[(16 + g) * SPP + 8 * ka + t];
            pa1[1] = Pme[(24 + g) * SPP + 8 * ka + t];
            pa1[2] = Pme[(16 + g) * SPP + 8 * ka + t + 4];
            pa1[3] = Pme[(24 + g) * SPP + 8 * ka + t + 4];
            #pragma unroll
            for (int na = 0; na < 8; na++) {
                float b0 = Vs[(8 * ka + t) * SVV + 8 * na + g];
                float b1 = Vs[(8 * ka + t + 4) * SVV + 8 * na + g];
                mma_tf32(O[0][na], pa0, b0, b1);
                mma_tf32(O[1][na], pa1, b0, b1);
            }
        }
        __syncthreads();   // everyone done with buffer (it&1) before refill

        // issue tile it+2 into the buffer just freed
        int nt = it + 2;
        if (nt < 64) {
            const float* kp = Kg + (size_t)nt * 64 * 64;
            const float* vp = Vg + (size_t)nt * 64 * 64;
            float* kd = Kb + (nt & 1) * 64 * SKK;
            float* vd = Vb + (nt & 1) * 64 * SVV;
            for (int idx = tid; idx < 1024; idx += 128) {
                int r = idx >> 4, c = idx & 15;
                asm volatile("cp.async.cg.shared.global [%0], [%1], 16;" ::
                    "r"(su32(kd + r * SKK + c * 4)), "l"(kp + r * 64 + c * 4));
                asm volatile("cp.async.cg.shared.global [%0], [%1], 16;" ::
                    "r"(su32(vd + r * SVV + c * 4)), "l"(vp + r * 64 + c * 4));
            }
        }
        asm volatile("cp.async.commit_group;");
    }

    // ---- epilogue ----
    #pragma unroll
    for (int rb = 0; rb < 2; rb++) {
        float i1 = 1.f / ls[rb][0], i2 = 1.f / ls[rb][1];
        int r1 = m0 + 32 * w + 16 * rb + g, r2 = r1 + 8;
        #pragma unroll
        for (int na = 0; na < 8; na++) {
            *(float2*)&g_o1[(size_t)(b * NN + r1) * 64 + 8 * na + 2 * t] =
                make_float2(O[rb][na][0] * i1, O[rb][na][1] * i1);
            *(float2*)&g_o1[(size_t)(b * NN + r2) * 64 + 8 * na + 2 * t] =
                make_float2(O[rb][na][2] * i2, O[rb][na][3] * i2);
        }
    }
}

// =====================================================================
// K4: channel attention scores (atomic accumulate over position tiles)
// =====================================================================
__global__ void k_chscore() {
    __shared__ float Qs[64][68];
    __shared__ float Ksm[64][68];
    int b  = blockIdx.y;
    int n0 = blockIdx.x * 64;
    int tid = threadIdx.x;
    int cg = tid & 15, r0 = tid >> 4;
    for (int rr = r0; rr < 64; rr += 16) {
        *(float4*)&Qs[rr][cg * 4] =
            *(const float4*)&g_q2[(size_t)(b * NN + n0 + rr) * 64 + cg * 4];
        *(float4*)&Ksm[rr][cg * 4] =
            *(const float4*)&g_k2[(size_t)(b * NN + n0 + rr) * 64 + cg * 4];
    }
    __syncthreads();
    int tx = tid & 15, ty = tid >> 4;
    float acc[4][4] = {};
    #pragma unroll 4
    for (int n = 0; n < 64; n++) {
        float4 qf = *(float4*)&Qs[n][ty * 4];
        float4 kf = *(float4*)&Ksm[n][tx * 4];
        float qa[4] = {qf.x, qf.y, qf.z, qf.w};
        float ka[4] = {kf.x, kf.y, kf.z, kf.w};
        #pragma unroll
        for (int i = 0; i < 4; i++)
            #pragma unroll
            for (int j = 0; j < 4; j++)
                acc[i][j] += qa[i] * ka[j];
    }
    #pragma unroll
    for (int i = 0; i < 4; i++)
        #pragma unroll
        for (int j = 0; j < 4; j++)
            atomicAdd(&g_s2[b * 4096 + (ty * 4 + i) * 64 + tx * 4 + j], acc[i][j]);
}

__global__ void k_chsoftmax_M(const float* __restrict__ w1) {
    __shared__ float qn[64][65];
    int b = blockIdx.x;
    int tid = threadIdx.x;
    int w = tid >> 5, lane = tid & 31;
    for (int r = w; r < 64; r += 8) {
        float v0 = g_s2[b * 4096 + r * 64 + lane];
        float v1 = g_s2[b * 4096 + r * 64 + 32 + lane];
        float m = fmaxf(v0, v1);
        #pragma unroll
        for (int off = 16; off; off >>= 1)
            m = fmaxf(m, __shfl_xor_sync(0xffffffffu, m, off));
        float e0 = __expf(v0 - m), e1 = __expf(v1 - m);
        float s = e0 + e1;
        #pragma unroll
        for (int off = 16; off; off >>= 1)
            s += __shfl_xor_sync(0xffffffffu, s, off);
        float inv = 1.f / s;
        qn[r][lane] = e0 * inv;
        qn[r][lane + 32] = e1 * inv;
    }
    __syncthreads();
    int tx = tid & 15, ty = tid >> 4;
    float acc[4][4] = {};
    #pragma unroll 4
    for (int c = 0; c < 64; c++) {
        float wv[4], qv[4];
        #pragma unroll
        for (int i = 0; i < 4; i++) wv[i] = w1[(ty * 4 + i) * 128 + 64 + c];
        #pragma unroll
        for (int j = 0; j < 4; j++) qv[j] = qn[c][tx * 4 + j];
        #pragma unroll
        for (int i = 0; i < 4; i++)
            #pragma unroll
            for (int j = 0; j < 4; j++)
                acc[i][j] += wv[i] * qv[j];
    }
    #pragma unroll
    for (int i = 0; i < 4; i++)
        #pragma unroll
        for (int j = 0; j < 4; j++)
            g_M[b * 4096 + (ty * 4 + i) * 64 + tx * 4 + j] = acc[i][j];
}

// =====================================================================
// K5: y = w1_left @ out1 + M @ v + b1
// =====================================================================
__global__ void k_proj(const float* __restrict__ w1, const float* __restrict__ b1) {
    __shared__ float As[64][68];
    __shared__ float Ws[64][65];
    int b  = blockIdx.y;
    int p0 = blockIdx.x * 64;
    int tid = threadIdx.x;
    int tx = tid & 15, ty = tid >> 4;
    float acc[4][4] = {};

    for (int ph = 0; ph < 2; ph++) {
        __syncthreads();
        int cg = tid & 15, r0 = tid >> 4;
        for (int rr = r0; rr < 64; rr += 16) {
            float4 av, wv;
            if (ph == 0) {
                av = *(const float4*)&g_o1[(size_t)(b * NN + p0 + rr) * 64 + cg * 4];
                wv = *(const float4*)&w1[rr * 128 + cg * 4];
            } else {
                av = *(const float4*)&g_v[(size_t)(b * NN + p0 + rr) * 64 + cg * 4];
                wv = *(const float4*)&g_M[b * 4096 + rr * 64 + cg * 4];
            }
            *(float4*)&As[rr][cg * 4] = av;
            Ws[rr][cg * 4 + 0] = wv.x; Ws[rr][cg * 4 + 1] = wv.y;
            Ws[rr][cg * 4 + 2] = wv.z; Ws[rr][cg * 4 + 3] = wv.w;
        }
        __syncthreads();
        #pragma unroll 8
        for (int c = 0; c < 64; c++) {
            float a[4], wv[4];
            #pragma unroll
            for (int i = 0; i < 4; i++) a[i]  = As[ty * 4 + i][c];
            #pragma unroll
            for (int j = 0; j < 4; j++) wv[j] = Ws[tx * 4 + j][c];
            #pragma unroll
            for (int i = 0; i < 4; i++)
                #pragma unroll
                for (int j = 0; j < 4; j++)
                    acc[i][j] += a[i] * wv[j];
        }
    }
    #pragma unroll
    for (int i = 0; i < 4; i++) {
        float4 o;
        o.x = acc[i][0] + b1[tx * 4 + 0];
        o.y = acc[i][1] + b1[tx * 4 + 1];
        o.z = acc[i][2] + b1[tx * 4 + 2];
        o.w = acc[i][3] + b1[tx * 4 + 3];
        *(float4*)&g_y[(size_t)(b * NN + p0 + ty * 4 + i) * 64 + tx * 4] = o;
    }
}

// =====================================================================
// K6: bilinear 2x upsample (half-pixel, edge clamp) + residual
// =====================================================================
__global__ void k_upsample(const float* __restrict__ x, float* __restrict__ out) {
    int idx = blockIdx.x * 256 + threadIdx.x;
    if (idx >= Bb * Cc * HH * WW) return;
    int j = idx & 127;
    int i = (idx >> 7) & 127;
    int c = (idx >> 14) & 63;
    int b = idx >> 20;
    int p = i >> 1, q = j >> 1;
    int r0, r1; float wy0, wy1;
    if (i & 1) { r0 = p; r1 = (p + 1 < 64) ? p + 1 : 63; wy0 = 0.75f; wy1 = 0.25f; }
    else       { r0 = (p > 0) ? p - 1 : 0; r1 = p;       wy0 = 0.25f; wy1 = 0.75f; }
    int s0, s1; float wx0, wx1;
    if (j & 1) { s0 = q; s1 = (q + 1 < 64) ? q + 1 : 63; wx0 = 0.75f; wx1 = 0.25f; }
    else       { s0 = (q > 0) ? q - 1 : 0; s1 = q;       wx0 = 0.25f; wx1 = 0.75f; }
    const float* yb = g_y + (size_t)b * NN * 64;
    float v = wy0 * (wx0 * yb[(r0 * 64 + s0) * 64 + c] + wx1 * yb[(r0 * 64 + s1) * 64 + c])
            + wy1 * (wx0 * yb[(r1 * 64 + s0) * 64 + c] + wx1 * yb[(r1 * 64 + s1) * 64 + c]);
    out[idx] = v + x[idx];
}

// =====================================================================
extern "C" void kernel_launch(void* const* d_in, const int* in_sizes, int n_in,
                              void* d_out, int out_size) {
    const float* x        = (const float*)d_in[0];
    const float* pm_gamma = (const float*)d_in[1];
    const float* pm_beta  = (const float*)d_in[2];
    const float* pm_w     = (const float*)d_in[3];
    const float* pm_b     = (const float*)d_in[4];
    const float* w2 = (const float*)d_in[5];
    const float* b2 = (const float*)d_in[6];
    const float* w3 = (const float*)d_in[7];
    const float* b3 = (const float*)d_in[8];
    const float* w4 = (const float*)d_in[9];
    const float* b4 = (const float*)d_in[10];
    const float* w5 = (const float*)d_in[11];
    const float* b5 = (const float*)d_in[12];
    const float* w6 = (const float*)d_in[13];
    const float* b6 = (const float*)d_in[14];
    const float* w1 = (const float*)d_in[15];
    const float* b1 = (const float*)d_in[16];
    float* out = (float*)d_out;

    const int merge_smem = (256 * 65 + 64 * 65) * 4;                       // 83200 B
    const int attn_smem  = (2 * 64 * SKK + 2 * 64 * SVV + 128 * SPP) * 4;  // 106496 B
    cudaFuncSetAttribute(k_merge_pml, cudaFuncAttributeMaxDynamicSharedMemorySize, merge_smem);
    cudaFuncSetAttribute(k_attn1_tc,  cudaFuncAttributeMaxDynamicSharedMemorySize, attn_smem);

    k_merge_pml  <<<dim3(64, Bb), 256, merge_smem>>>(x, pm_gamma, pm_beta, pm_w, pm_b);
    k_qkv5       <<<dim3(64, Bb), 256>>>(w2, b2, w3, b3, w4, b4, w5, b5, w6, b6);
    k_attn1_tc   <<<dim3(32, Bb), 128, attn_smem>>>();
    k_chscore    <<<dim3(64, Bb), 256>>>();
    k_chsoftmax_M<<<Bb, 256>>>(w1);
    k_proj       <<<dim3(64, Bb), 256>>>(w1, b1);
    k_upsample   <<<(Bb * Cc * HH * WW) / 256, 256>>>(x, out);
}